// round 12
// baseline (speedup 1.0000x reference)
#include <cuda_runtime.h>
#include <cuda_bf16.h>
#include <math.h>
#include <stdint.h>

typedef __nv_bfloat16 bf16;

// ---------------- problem constants ----------------
#define DMODEL 1024
#define NHEAD  4
#define HDIM   256
#define TLEN   512
#define V3DIM  15069
#define KVPAD  15104
#define DFFDIM 2048
#define AUDDIM 768

// ---------------- fp32 scratch ----------------
__device__ float g_style [DMODEL];
__device__ float g_x     [TLEN * DMODEL];
__device__ float g_y     [TLEN * DMODEL];
__device__ float g_qkv   [TLEN * 3 * DMODEL];
__device__ float g_part  [5 * 1024 * 1024];   // split-K partials (max 4.72M floats)
__device__ int   g_cnt   [64];                // per-tile arrival counters (zero-init)

// ---------------- bf16 hi/lo buffers ----------------
__device__ bf16 g_Waf_h [DMODEL * AUDDIM],  g_Waf_l [DMODEL * AUDDIM];
__device__ bf16 g_Wvm_h [DMODEL * KVPAD],   g_Wvm_l [DMODEL * KVPAD];
__device__ bf16 g_Wqkv_h[3 * DMODEL * DMODEL], g_Wqkv_l[3 * DMODEL * DMODEL];
__device__ bf16 g_Wosa_h[DMODEL * DMODEL],  g_Wosa_l[DMODEL * DMODEL];
__device__ bf16 g_Wvca_h[DMODEL * DMODEL],  g_Wvca_l[DMODEL * DMODEL];
__device__ bf16 g_Woca_h[DMODEL * DMODEL],  g_Woca_l[DMODEL * DMODEL];
__device__ bf16 g_W1_h  [DFFDIM * DMODEL],  g_W1_l  [DFFDIM * DMODEL];
__device__ bf16 g_W2_h  [DMODEL * DFFDIM],  g_W2_l  [DMODEL * DFFDIM];
__device__ bf16 g_Wvr_h [V3DIM * DMODEL],   g_Wvr_l [V3DIM * DMODEL];

__device__ bf16 g_aud_h [TLEN * AUDDIM],  g_aud_l [TLEN * AUDDIM];
__device__ bf16 g_vin_h [TLEN * KVPAD],   g_vin_l [TLEN * KVPAD];
__device__ bf16 g_hid_h [TLEN * DMODEL],  g_hid_l [TLEN * DMODEL];
__device__ bf16 g_xa_h  [TLEN * DMODEL],  g_xa_l  [TLEN * DMODEL];
__device__ bf16 g_x2_h  [TLEN * DMODEL],  g_x2_l  [TLEN * DMODEL];
__device__ bf16 g_y2_h  [TLEN * DMODEL],  g_y2_l  [TLEN * DMODEL];
__device__ bf16 g_attn_h[TLEN * DMODEL],  g_attn_l[TLEN * DMODEL];
__device__ bf16 g_vca_h [TLEN * DMODEL],  g_vca_l [TLEN * DMODEL];
__device__ bf16 g_ff_h  [TLEN * DFFDIM],  g_ff_l  [TLEN * DFFDIM];

// ---------------- helpers ----------------
__device__ __forceinline__ uint32_t smem_u32(const void* p){
    uint32_t a;
    asm("{ .reg .u64 t; cvta.to.shared.u64 t, %1; cvt.u32.u64 %0, t; }" : "=r"(a) : "l"(p));
    return a;
}
__device__ __forceinline__ void cp_async16(uint32_t dst, const void* src, uint32_t sz){
    asm volatile("cp.async.cg.shared.global [%0], [%1], 16, %2;" :: "r"(dst), "l"(src), "r"(sz));
}
__device__ __forceinline__ void cp_commit(){
    asm volatile("cp.async.commit_group;" ::: "memory");
}
__device__ __forceinline__ void cp_wait(int allow){
    if (allow <= 0)      asm volatile("cp.async.wait_group 0;" ::: "memory");
    else if (allow == 1) asm volatile("cp.async.wait_group 1;" ::: "memory");
    else                 asm volatile("cp.async.wait_group 2;" ::: "memory");
}
__device__ __forceinline__ void ldsm4(uint32_t& r0, uint32_t& r1, uint32_t& r2,
                                      uint32_t& r3, uint32_t addr){
    asm volatile("ldmatrix.sync.aligned.m8n8.x4.shared.b16 {%0,%1,%2,%3}, [%4];"
        : "=r"(r0), "=r"(r1), "=r"(r2), "=r"(r3) : "r"(addr));
}
__device__ __forceinline__ void split_write(bf16* hi, bf16* lo, size_t o, float v){
    bf16 h = __float2bfloat16(v);
    hi[o] = h;
    lo[o] = __float2bfloat16(v - __bfloat162float(h));
}
__device__ __forceinline__ uint32_t pk2(float a, float b){
    __nv_bfloat162 t(__float2bfloat16(a), __float2bfloat16(b));
    uint32_t u; memcpy(&u, &t, 4); return u;
}

// ---------------- epilogue ----------------
// EM: 0=+bias ; 1=+bias,relu ; 2=+bias,+resid ; 3=+bias,+style,+PE ; 4=+bias,+template[n]
template<int EM>
__device__ __forceinline__ float apply_epi(float v, int gm, int gn,
    const float* bias, const float* resid, const float* e_aux, int N)
{
    v += bias[gn];
    if (EM == 1) v = fmaxf(v, 0.0f);
    if (EM == 2) v += resid[(size_t)gm * N + gn];
    if (EM == 3) {
        v += e_aux[gn];
        int   p   = gm % 25;
        int   e   = gn & ~1;
        float dv  = expf((float)e * (-9.210340371976184f / 1024.0f));
        float ang = (float)p * dv;
        v += (gn & 1) ? cosf(ang) : sinf(ang);
    }
    if (EM == 4) v += e_aux[gn];
    return v;
}

// ---------------- merged conversion kernel ----------------
#define NJOBS 11
struct ConvJobs {
    const float* src[NJOBS];
    bf16* hi[NJOBS];
    bf16* lo[NJOBS];
    int   K[NJOBS];
    int   Kpad[NJOBS];
    int   rows[NJOBS];
    int   mode[NJOBS];
    int   blk_end[NJOBS];
    const float* tmpl;
};

__global__ void __launch_bounds__(256) conv_all(ConvJobs J)
{
    int b = blockIdx.x;
    int j = 0;
#pragma unroll
    for (int t = 0; t < NJOBS; t++) if (b >= J.blk_end[t]) j = t + 1;
    int b0   = (j == 0) ? 0 : J.blk_end[j - 1];
    long e0  = (long)(b - b0) * 2048 + threadIdx.x * 8;
    int Kpad = J.Kpad[j], K = J.K[j];
    if (e0 >= (long)J.rows[j] * Kpad) return;
    const float* src = J.src[j];
    int mode = J.mode[j];

#pragma unroll
    for (int half = 0; half < 2; half++) {
        long e   = e0 + half * 4;
        int row  = (int)(e / Kpad);
        int kp   = (int)(e - (long)row * Kpad);
        float v[4];
        if (mode == 1) {
            if (row == 0) { v[0]=v[1]=v[2]=v[3]=0.0f; }
            else {
                const float* s = src + (size_t)(row - 1) * K;
#pragma unroll
                for (int i = 0; i < 4; i++) {
                    int k = kp + i;
                    v[i] = (k < K) ? s[k] - J.tmpl[k] : 0.0f;
                }
            }
        } else {
            const float* s = src + (size_t)row * K;
#pragma unroll
            for (int i = 0; i < 4; i++) {
                int k = kp + i;
                v[i] = (k < K) ? s[k] : 0.0f;
            }
        }
        float h0 = __bfloat162float(__float2bfloat16(v[0]));
        float h1 = __bfloat162float(__float2bfloat16(v[1]));
        float h2 = __bfloat162float(__float2bfloat16(v[2]));
        float h3 = __bfloat162float(__float2bfloat16(v[3]));
        size_t o = (size_t)row * Kpad + kp;
        *(uint2*)(J.hi[j] + o) = make_uint2(pk2(h0, h1), pk2(h2, h3));
        *(uint2*)(J.lo[j] + o) = make_uint2(pk2(v[0]-h0, v[1]-h1), pk2(v[2]-h2, v[3]-h3));
    }
}

// ---------------- mma machinery ----------------
__device__ __forceinline__ void mma16816(float* c,
    uint32_t a0, uint32_t a1, uint32_t a2, uint32_t a3,
    uint32_t b0, uint32_t b1)
{
    asm volatile("mma.sync.aligned.m16n8k16.row.col.f32.bf16.bf16.f32 "
        "{%0,%1,%2,%3}, {%4,%5,%6,%7}, {%8,%9}, {%0,%1,%2,%3};"
        : "+f"(c[0]), "+f"(c[1]), "+f"(c[2]), "+f"(c[3])
        : "r"(a0), "r"(a1), "r"(a2), "r"(a3), "r"(b0), "r"(b1));
}

#define ROWB 80

// ============ GEMM: 128x256 tile, 8 warps, split-K + in-kernel fused reduce ============
#define BA_T  (128 * ROWB)
#define BB_T  (256 * ROWB)
#define BSTG  (2 * BA_T + 2 * BB_T)
#define BNST  3
#define BSM_BYTES (BNST * BSTG)   // 184320

__device__ __forceinline__ void compute_chunk_b(uint32_t sb, int wm, int wn,
                                                int lane, float (&acc)[4][8][4])
{
    int g    = lane & 7;
    int quad = lane >> 3;
    uint32_t a_r = g + 8 * (quad & 1);
    uint32_t a_c = 16 * (quad >> 1);
    uint32_t b_r = g + 8 * (quad >> 1);
    uint32_t b_c = 16 * (quad & 1);
    uint32_t sAh = sb;
    uint32_t sBh = sb + 2 * BA_T;

#pragma unroll
    for (int ks = 0; ks < 2; ks++) {
        uint32_t kb = ks * 32;
        uint32_t ah[4][4], al[4][4];
#pragma unroll
        for (int mt = 0; mt < 4; mt++) {
            uint32_t ad = sAh + (wm*64 + mt*16 + a_r) * ROWB + kb + a_c;
            ldsm4(ah[mt][0], ah[mt][1], ah[mt][2], ah[mt][3], ad);
            ldsm4(al[mt][0], al[mt][1], al[mt][2], al[mt][3], ad + BA_T);
        }
#pragma unroll
        for (int nh = 0; nh < 2; nh++) {
            uint32_t bh[4][2], bl[4][2];
#pragma unroll
            for (int p = 0; p < 2; p++) {
                uint32_t bd = sBh + (wn*64 + (nh*4 + p*2)*8 + b_r) * ROWB + kb + b_c;
                ldsm4(bh[p*2][0], bh[p*2][1], bh[p*2+1][0], bh[p*2+1][1], bd);
                ldsm4(bl[p*2][0], bl[p*2][1], bl[p*2+1][0], bl[p*2+1][1], bd + BB_T);
            }
#pragma unroll
            for (int mt = 0; mt < 4; mt++) {
#pragma unroll
                for (int q = 0; q < 4; q++) {
                    float* c = acc[mt][nh*4 + q];
                    mma16816(c, ah[mt][0], ah[mt][1], ah[mt][2], ah[mt][3],
                             bh[q][0], bh[q][1]);
                    mma16816(c, ah[mt][0], ah[mt][1], ah[mt][2], ah[mt][3],
                             bl[q][0], bl[q][1]);
                    mma16816(c, al[mt][0], al[mt][1], al[mt][2], al[mt][3],
                             bh[q][0], bh[q][1]);
                }
            }
        }
    }
}

__device__ __forceinline__ void stage_copy_b(uint32_t sb32, int stage,
    const bf16* __restrict__ Ah, const bf16* __restrict__ Al,
    const bf16* __restrict__ Bh, const bf16* __restrict__ Bl,
    int bm, int bn, int N, int Kpad, int kk, int tid)
{
    uint32_t st = sb32 + stage * BSTG;
#pragma unroll
    for (int c = 0; c < 12; c++) {
        int g   = c * 256 + tid;
        int col = g & 3;
        int r   = g >> 2;
        uint32_t dst; const bf16* base; int rowg; uint32_t sz = 16;
        if (r < 256) {
            int tile = r >> 7, row = r & 127;
            dst  = st + tile * BA_T + row * ROWB + col * 16;
            base = tile ? Al : Ah;
            rowg = bm + row;
        } else {
            int r2 = r - 256;
            int tile = r2 >> 8, row = r2 & 255;
            dst  = st + 2 * BA_T + tile * BB_T + row * ROWB + col * 16;
            base = tile ? Bl : Bh;
            rowg = bn + row;
            if (rowg >= N) { rowg = 0; sz = 0; }
        }
        cp_async16(dst, base + (size_t)rowg * Kpad + kk + col * 8, sz);
    }
}

// split-K gemm; the last-arriving CTA per tile reduces all z-slices and applies
// the epilogue (deterministic: fixed z order), then resets the counter.
template<int EM>
__global__ void __launch_bounds__(256, 1) gemm_b(
    const bf16* __restrict__ Ah, const bf16* __restrict__ Al,
    const bf16* __restrict__ Bh, const bf16* __restrict__ Bl,
    const float* __restrict__ bias, const float* __restrict__ resid,
    const float* __restrict__ e_aux,
    float* __restrict__ C, bf16* __restrict__ Chi, bf16* __restrict__ Clo,
    float* __restrict__ Cpart, int* __restrict__ cnt,
    int M, int N, int Kpad, int nchunks, int nsplit)
{
    extern __shared__ __align__(16) char smem[];
    uint32_t sb32 = smem_u32(smem);
    int tid  = threadIdx.x;
    int wid  = tid >> 5, lane = tid & 31;
    int wm   = wid >> 2, wn = wid & 3;
    int bm   = blockIdx.y * 128, bn = blockIdx.x * 256;
    int cpz  = (nchunks + nsplit - 1) / nsplit;
    int c0   = blockIdx.z * cpz;
    int c1   = min(nchunks, c0 + cpz);
    int nloc = c1 - c0;

    float acc[4][8][4];
#pragma unroll
    for (int a = 0; a < 4; a++)
#pragma unroll
        for (int b = 0; b < 8; b++)
#pragma unroll
            for (int c = 0; c < 4; c++) acc[a][b][c] = 0.0f;

    int npre = min(BNST, nloc);
    for (int s = 0; s < npre; s++) {
        stage_copy_b(sb32, s, Ah, Al, Bh, Bl, bm, bn, N, Kpad, (c0 + s) * 32, tid);
        cp_commit();
    }

    for (int j = 0; j < nloc; j++) {
        cp_wait(min(nloc - 1 - j, BNST - 1));
        __syncthreads();
        compute_chunk_b(sb32 + (j % BNST) * BSTG, wm, wn, lane, acc);
        __syncthreads();
        if (j + BNST < nloc) {
            stage_copy_b(sb32, j % BNST, Ah, Al, Bh, Bl, bm, bn, N, Kpad,
                         (c0 + j + BNST) * 32, tid);
            cp_commit();
        }
    }

    int l4 = lane >> 2, lt = lane & 3;

    if (nsplit == 1) {
#pragma unroll
        for (int mt = 0; mt < 4; mt++) {
#pragma unroll
            for (int nt = 0; nt < 8; nt++) {
                int r0 = bm + wm * 64 + mt * 16 + l4;
                int cc = bn + wn * 64 + nt * 8 + lt * 2;
                float* a4 = acc[mt][nt];
#pragma unroll
                for (int e = 0; e < 4; e++) {
                    int gm = r0 + (e >> 1) * 8;
                    int gn = cc + (e & 1);
                    if (gn < N) {
                        float v = apply_epi<EM>(a4[e], gm, gn, bias, resid, e_aux, N);
                        if (C)   C[(size_t)gm * N + gn] = v;
                        if (Chi) split_write(Chi, Clo, (size_t)gm * N + gn, v);
                    }
                }
            }
        }
        return;
    }

    // ---- write partials ----
    {
        float* P = Cpart + (size_t)blockIdx.z * M * N;
#pragma unroll
        for (int mt = 0; mt < 4; mt++) {
#pragma unroll
            for (int nt = 0; nt < 8; nt++) {
                int r0 = bm + wm * 64 + mt * 16 + l4;
                int cc = bn + wn * 64 + nt * 8 + lt * 2;
                float* a4 = acc[mt][nt];
                if (cc < N) {
                    P[(size_t)r0 * N + cc]       = a4[0];
                    P[(size_t)(r0 + 8) * N + cc] = a4[2];
                }
                if (cc + 1 < N) {
                    P[(size_t)r0 * N + cc + 1]       = a4[1];
                    P[(size_t)(r0 + 8) * N + cc + 1] = a4[3];
                }
            }
        }
    }

    // ---- arrival count; last CTA reduces (threadFenceReduction pattern) ----
    __shared__ int s_old;
    __syncthreads();
    if (tid == 0) {
        __threadfence();
        s_old = atomicAdd(&cnt[blockIdx.y * gridDim.x + blockIdx.x], 1);
    }
    __syncthreads();
    if (s_old != nsplit - 1) return;

    if (tid == 0) cnt[blockIdx.y * gridDim.x + blockIdx.x] = 0;
    __threadfence();   // order: our reads of partials after observing all arrivals

    for (int idx = tid; idx < 128 * 256; idx += 256) {
        int r  = idx >> 8, c = idx & 255;
        int gm = bm + r, gn = bn + c;
        if (gn >= N) continue;
        float s = 0.0f;
        for (int z = 0; z < nsplit; z++)
            s += Cpart[(size_t)z * M * N + (size_t)gm * N + gn];
        float v = apply_epi<EM>(s, gm, gn, bias, resid, e_aux, N);
        size_t o = (size_t)gm * N + gn;
        if (C)   C[o] = v;
        if (Chi) split_write(Chi, Clo, o, v);
    }
}

// ---------------- style ----------------
__global__ void style_k(const float* __restrict__ oh, const float* __restrict__ W,
                        float* __restrict__ st)
{
    int d = blockIdx.x * blockDim.x + threadIdx.x;
    if (d < DMODEL) {
        float s = 0.0f;
#pragma unroll
        for (int n = 0; n < 8; n++) s += oh[n] * W[d * 8 + n];
        st[d] = s;
    }
}

// ---------------- LayerNorm ----------------
__device__ __forceinline__ float block_sum(float v, float* sred)
{
    __syncthreads();
#pragma unroll
    for (int o = 16; o; o >>= 1) v += __shfl_xor_sync(0xffffffffu, v, o);
    int w = threadIdx.x >> 5, l = threadIdx.x & 31;
    if (l == 0) sred[w] = v;
    __syncthreads();
    float t = (l < 8) ? sred[l] : 0.0f;
#pragma unroll
    for (int o = 4; o; o >>= 1) t += __shfl_xor_sync(0xffffffffu, t, o);
    if (threadIdx.x == 0) sred[0] = t;
    __syncthreads();
    return sred[0];
}

__global__ void __launch_bounds__(256) layernorm_k(float* __restrict__ x,
    const float* __restrict__ g, const float* __restrict__ b,
    bf16* __restrict__ hi, bf16* __restrict__ lo)
{
    __shared__ float sred[32];
    int row = blockIdx.x, tid = threadIdx.x;
    float v[4];
    float s = 0.0f;
#pragma unroll
    for (int i = 0; i < 4; i++) { v[i] = x[row * DMODEL + i * 256 + tid]; s += v[i]; }
    float mean = block_sum(s, sred) * (1.0f / 1024.0f);
    float sq = 0.0f;
#pragma unroll
    for (int i = 0; i < 4; i++) { float d = v[i] - mean; sq += d * d; }
    float var  = block_sum(sq, sred) * (1.0f / 1024.0f);
    float rstd = rsqrtf(var + 1e-5f);
#pragma unroll
    for (int i = 0; i < 4; i++) {
        int c = i * 256 + tid;
        float o = (v[i] - mean) * rstd * g[c] + b[c];
        x[row * DMODEL + c] = o;
        if (hi) split_write(hi, lo, (size_t)row * DMODEL + c, o);
    }
}

// ---------------- fused self-attention ----------------
#define ATT_BQ 16
#define ATT_KT 64
#define SPAD   516
#define QS_FLOATS (256 * 17)
#define SS_FLOATS (ATT_BQ * SPAD)
#define KV_FLOATS (256 * 68)
#define ATT_SMEM_BYTES ((QS_FLOATS + SS_FLOATS + KV_FLOATS) * 4)

__global__ void __launch_bounds__(256) attention_sa(const float* __restrict__ qkv,
                                                    bf16* __restrict__ ohi,
                                                    bf16* __restrict__ olo)
{
    extern __shared__ __align__(16) float sm[];
    float* Qs = sm;
    float* Ss = sm + QS_FLOATS;
    float* KV = sm + QS_FLOATS + SS_FLOATS;

    int h   = blockIdx.y;
    int q0  = blockIdx.x * ATT_BQ;
    int tid = threadIdx.x;
    float slope = exp2f(-2.0f * (float)(h + 1));

    for (int idx = tid; idx < ATT_BQ * 256; idx += 256) {
        int qi = idx >> 8, d = idx & 255;
        Qs[d * 17 + qi] = qkv[(size_t)(q0 + qi) * 3072 + h * 256 + d];
    }
    __syncthreads();

    int qmax = q0 + ATT_BQ - 1;
    int qi   = tid >> 4;

    {
        int kk0 = (tid & 15) * 4;
        for (int s0 = 0; s0 < TLEN; s0 += ATT_KT) {
            if (s0 > qmax) {
                for (int idx = tid; idx < ATT_BQ * ATT_KT; idx += 256) {
                    int rr = idx >> 6, cc = idx & 63;
                    Ss[rr * SPAD + s0 + cc] = -1e30f;
                }
                continue;
            }
            for (int idx = tid; idx < ATT_KT * 256; idx += 256) {
                int kk = idx >> 8, d = idx & 255;
                KV[d * 68 + kk] = qkv[(size_t)(s0 + kk) * 3072 + 1024 + h * 256 + d];
            }
            __syncthreads();
            float a0 = 0.f, a1 = 0.f, a2 = 0.f, a3 = 0.f;
#pragma unroll 4
            for (int d = 0; d < 256; d++) {
                float  qv = Qs[d * 17 + qi];
                float4 kv = *(const float4*)&KV[d * 68 + kk0];
                a0 = fmaf(qv, kv.x, a0);
                a1 = fmaf(qv, kv.y, a1);
                a2 = fmaf(qv, kv.z, a2);
                a3 = fmaf(qv, kv.w, a3);
            }
            int i  = q0 + qi;
            int jb = s0 + kk0;
            float accs[4] = {a0, a1, a2, a3};
#pragma unroll
            for (int c = 0; c < 4; c++) {
                int jj = jb + c;
                float mv = (jj > i) ? -1e30f : (-slope * (float)((i - jj) / 25));
                Ss[qi * SPAD + jj] = accs[c] * 0.0625f + mv;
            }
            __syncthreads();
        }
    }
    __syncthreads();

    {
        int warp = tid >> 5, lane = tid & 31;
        for (int rr = warp; rr < ATT_BQ; rr += 8) {
            float mx = -1e30f;
            for (int jj = lane; jj < TLEN; jj += 32) mx = fmaxf(mx, Ss[rr * SPAD + jj]);
#pragma unroll
            for (int o = 16; o; o >>= 1) mx = fmaxf(mx, __shfl_xor_sync(0xffffffffu, mx, o));
            float sum = 0.0f;
            for (int jj = lane; jj < TLEN; jj += 32) {
                float e = expf(Ss[rr * SPAD + jj] - mx);
                Ss[rr * SPAD + jj] = e;
                sum += e;
            }
#pragma unroll
            for (int o = 16; o; o >>= 1) sum += __shfl_xor_sync(0xffffffffu, sum, o);
            float inv = 1.0f / sum;
            for (int jj = lane; jj < TLEN; jj += 32) Ss[rr * SPAD + jj] *= inv;
        }
    }
    __syncthreads();

    float acc[16];
#pragma unroll
    for (int i = 0; i < 16; i++) acc[i] = 0.0f;
    int d0 = (tid & 15) * 16;

    for (int s0 = 0; s0 <= qmax; s0 += ATT_KT) {
        for (int idx = tid; idx < ATT_KT * 256; idx += 256) {
            int kk = idx >> 8, d = idx & 255;
            KV[kk * 256 + d] = qkv[(size_t)(s0 + kk) * 3072 + 2048 + h * 256 + d];
        }
        __syncthreads();
        for (int kk = 0; kk < ATT_KT; kk++) {
            float a = Ss[qi * SPAD + s0 + kk];
            const float4* vp = (const float4*)&KV[kk * 256 + d0];
            float4 v0 = vp[0], v1 = vp[1], v2 = vp[2], v3 = vp[3];
            acc[0]  = fmaf(a, v0.x, acc[0]);  acc[1]  = fmaf(a, v0.y, acc[1]);
            acc[2]  = fmaf(a, v0.z, acc[2]);  acc[3]  = fmaf(a, v0.w, acc[3]);
            acc[4]  = fmaf(a, v1.x, acc[4]);  acc[5]  = fmaf(a, v1.y, acc[5]);
            acc[6]  = fmaf(a, v1.z, acc[6]);  acc[7]  = fmaf(a, v1.w, acc[7]);
            acc[8]  = fmaf(a, v2.x, acc[8]);  acc[9]  = fmaf(a, v2.y, acc[9]);
            acc[10] = fmaf(a, v2.z, acc[10]); acc[11] = fmaf(a, v2.w, acc[11]);
            acc[12] = fmaf(a, v3.x, acc[12]); acc[13] = fmaf(a, v3.y, acc[13]);
            acc[14] = fmaf(a, v3.z, acc[14]); acc[15] = fmaf(a, v3.w, acc[15]);
        }
        __syncthreads();
    }
#pragma unroll
    for (int c = 0; c < 16; c++)
        split_write(ohi, olo, (size_t)(q0 + qi) * 1024 + h * 256 + d0 + c, acc[c]);
}

// ---------------- launcher (15 launches, no reduce kernels) ----------------
extern "C" void kernel_launch(void* const* d_in, const int* in_sizes, int n_in,
                              void* d_out, int out_size)
{
    const float* audio   = (const float*)d_in[0];
    const float* vertice = (const float*)d_in[1];
    const float* tmpl    = (const float*)d_in[2];
    const float* one_hot = (const float*)d_in[3];
    const float* W_af    = (const float*)d_in[4];
    const float* b_af    = (const float*)d_in[5];
    const float* W_vm    = (const float*)d_in[6];
    const float* b_vm    = (const float*)d_in[7];
    const float* W_obj   = (const float*)d_in[8];
    const float* Wqkv_sa = (const float*)d_in[9];
    const float* bqkv_sa = (const float*)d_in[10];
    const float* Wo_sa   = (const float*)d_in[11];
    const float* bo_sa   = (const float*)d_in[12];
    const float* Wqkv_ca = (const float*)d_in[13];
    const float* bqkv_ca = (const float*)d_in[14];
    const float* Wo_ca   = (const float*)d_in[15];
    const float* bo_ca   = (const float*)d_in[16];
    const float* W1      = (const float*)d_in[17];
    const float* b1      = (const float*)d_in[18];
    const float* W2      = (const float*)d_in[19];
    const float* b2      = (const float*)d_in[20];
    const float* g1      = (const float*)d_in[21];
    const float* be1     = (const float*)d_in[22];
    const float* g2      = (const float*)d_in[23];
    const float* be2     = (const float*)d_in[24];
    const float* g3      = (const float*)d_in[25];
    const float* be3     = (const float*)d_in[26];
    const float* W_vr    = (const float*)d_in[27];
    const float* b_vr    = (const float*)d_in[28];
    float* out = (float*)d_out;

    float *style, *x, *y, *qkv, *part;
    int* cnt;
    cudaGetSymbolAddress((void**)&style, g_style);
    cudaGetSymbolAddress((void**)&x,     g_x);
    cudaGetSymbolAddress((void**)&y,     g_y);
    cudaGetSymbolAddress((void**)&qkv,   g_qkv);
    cudaGetSymbolAddress((void**)&part,  g_part);
    cudaGetSymbolAddress((void**)&cnt,   g_cnt);

#define SYM(p, s) bf16* p; cudaGetSymbolAddress((void**)&p, s)
    SYM(Waf_h, g_Waf_h);  SYM(Waf_l, g_Waf_l);
    SYM(Wvm_h, g_Wvm_h);  SYM(Wvm_l, g_Wvm_l);
    SYM(Wqkv_h, g_Wqkv_h); SYM(Wqkv_l, g_Wqkv_l);
    SYM(Wosa_h, g_Wosa_h); SYM(Wosa_l, g_Wosa_l);
    SYM(Wvca_h, g_Wvca_h); SYM(Wvca_l, g_Wvca_l);
    SYM(Woca_h, g_Woca_h); SYM(Woca_l, g_Woca_l);
    SYM(W1_h, g_W1_h);    SYM(W1_l, g_W1_l);
    SYM(W2_h, g_W2_h);    SYM(W2_l, g_W2_l);
    SYM(Wvr_h, g_Wvr_h);  SYM(Wvr_l, g_Wvr_l);
    SYM(aud_h, g_aud_h);  SYM(aud_l, g_aud_l);
    SYM(vin_h, g_vin_h);  SYM(vin_l, g_vin_l);
    SYM(hid_h, g_hid_h);  SYM(hid_l, g_hid_l);
    SYM(xa_h, g_xa_h);    SYM(xa_l, g_xa_l);
    SYM(x2_h, g_x2_h);    SYM(x2_l, g_x2_l);
    SYM(y2_h, g_y2_h);    SYM(y2_l, g_y2_l);
    SYM(attn_h, g_attn_h); SYM(attn_l, g_attn_l);
    SYM(vca_h, g_vca_h);  SYM(vca_l, g_vca_l);
    SYM(ff_h, g_ff_h);    SYM(ff_l, g_ff_l);
#undef SYM

    cudaFuncSetAttribute(attention_sa,
        cudaFuncAttributeMaxDynamicSharedMemorySize, ATT_SMEM_BYTES);
    cudaFuncSetAttribute(gemm_b<0>, cudaFuncAttributeMaxDynamicSharedMemorySize, BSM_BYTES);
    cudaFuncSetAttribute(gemm_b<1>, cudaFuncAttributeMaxDynamicSharedMemorySize, BSM_BYTES);
    cudaFuncSetAttribute(gemm_b<2>, cudaFuncAttributeMaxDynamicSharedMemorySize, BSM_BYTES);
    cudaFuncSetAttribute(gemm_b<3>, cudaFuncAttributeMaxDynamicSharedMemorySize, BSM_BYTES);
    cudaFuncSetAttribute(gemm_b<4>, cudaFuncAttributeMaxDynamicSharedMemorySize, BSM_BYTES);

    const int M = TLEN;

    // ---- conversion ----
    {
        ConvJobs J;
        J.tmpl = tmpl;
        const float* srcs[NJOBS] = { W_af, audio, W_vm, vertice, Wqkv_sa,
                                     Wo_sa, Wqkv_ca + (size_t)2048*DMODEL, Wo_ca,
                                     W1, W2, W_vr };
        bf16* his[NJOBS] = { Waf_h, aud_h, Wvm_h, vin_h, Wqkv_h, Wosa_h, Wvca_h,
                             Woca_h, W1_h, W2_h, Wvr_h };
        bf16* los[NJOBS] = { Waf_l, aud_l, Wvm_l, vin_l, Wqkv_l, Wosa_l, Wvca_l,
                             Woca_l, W1_l, W2_l, Wvr_l };
        int Ks[NJOBS]    = { AUDDIM, AUDDIM, V3DIM, V3DIM, DMODEL, DMODEL, DMODEL,
                             DMODEL, DMODEL, DFFDIM, DMODEL };
        int Kps[NJOBS]   = { AUDDIM, AUDDIM, KVPAD, KVPAD, DMODEL, DMODEL, DMODEL,
                             DMODEL, DMODEL, DFFDIM, DMODEL };
        int rows[NJOBS]  = { DMODEL, TLEN, DMODEL, TLEN, 3*DMODEL, DMODEL, DMODEL,
                             DMODEL, DFFDIM, DMODEL, V3DIM };
        int modes[NJOBS] = { 0, 0, 0, 1, 0, 0, 0, 0, 0, 0, 0 };
        int nb = 0;
        for (int t = 0; t < NJOBS; t++) {
            J.src[t] = srcs[t]; J.hi[t] = his[t]; J.lo[t] = los[t];
            J.K[t] = Ks[t]; J.Kpad[t] = Kps[t]; J.rows[t] = rows[t];
            J.mode[t] = modes[t];
            nb += (int)(((long)rows[t] * Kps[t] + 2047) / 2048);
            J.blk_end[t] = nb;
        }
        conv_all<<<nb, 256>>>(J);
    }
    style_k<<<4, 256>>>(one_hot, W_obj, style);

    // ---- x/xa = vin @ W_vm^T + b_vm + style + PE  (split 9, fused reduce) ----
    gemm_b<3><<<dim3(4,4,9), 256, BSM_BYTES>>>(
        vin_h, vin_l, Wvm_h, Wvm_l, b_vm, nullptr, style,
        x, xa_h, xa_l, part, cnt, M, DMODEL, KVPAD, 472, 9);

    // ---- hid = audio @ W_af^T + b_af  (split 6) ----
    gemm_b<0><<<dim3(4,4,6), 256, BSM_BYTES>>>(
        aud_h, aud_l, Waf_h, Waf_l, b_af, nullptr, nullptr,
        nullptr, hid_h, hid_l, part, cnt, M, DMODEL, AUDDIM, 24, 6);

    // ---- vca = hid @ Wv_ca^T + bv  (split 8) ----
    gemm_b<0><<<dim3(4,4,8), 256, BSM_BYTES>>>(
        hid_h, hid_l, Wvca_h, Wvca_l, bqkv_ca + 2048, nullptr, nullptr,
        nullptr, vca_h, vca_l, part, cnt, M, DMODEL, DMODEL, 32, 8);

    // ---- qkv = xa @ Wqkv^T + bqkv  (split 3) ----
    gemm_b<0><<<dim3(12,4,3), 256, BSM_BYTES>>>(
        xa_h, xa_l, Wqkv_h, Wqkv_l, bqkv_sa, nullptr, nullptr,
        qkv, nullptr, nullptr, part, cnt, M, 3*DMODEL, DMODEL, 32, 3);

    attention_sa<<<dim3(TLEN/ATT_BQ, NHEAD), 256, ATT_SMEM_BYTES>>>(qkv, attn_h, attn_l);

    // ---- y = x + attn @ Wo_sa^T + bo_sa ; LN1 ----
    gemm_b<2><<<dim3(4,4,8), 256, BSM_BYTES>>>(
        attn_h, attn_l, Wosa_h, Wosa_l, bo_sa, x, nullptr,
        y, nullptr, nullptr, part, cnt, M, DMODEL, DMODEL, 32, 8);
    layernorm_k<<<M, 256>>>(y, g1, be1, nullptr, nullptr);

    // ---- x = y + vca @ Wo_ca^T + bo_ca ; LN2 (+hi/lo) ----
    gemm_b<2><<<dim3(4,4,8), 256, BSM_BYTES>>>(
        vca_h, vca_l, Woca_h, Woca_l, bo_ca, y, nullptr,
        x, nullptr, nullptr, part, cnt, M, DMODEL, DMODEL, 32, 8);
    layernorm_k<<<M, 256>>>(x, g2, be2, x2_h, x2_l);

    // ---- FFN ----
    gemm_b<1><<<dim3(8,4,4), 256, BSM_BYTES>>>(
        x2_h, x2_l, W1_h, W1_l, b1, nullptr, nullptr,
        nullptr, ff_h, ff_l, part, cnt, M, DFFDIM, DMODEL, 32, 4);
    gemm_b<2><<<dim3(4,4,8), 256, BSM_BYTES>>>(
        ff_h, ff_l, W2_h, W2_l, b2, x, nullptr,
        y, nullptr, nullptr, part, cnt, M, DMODEL, DFFDIM, 64, 8);
    layernorm_k<<<M, 256>>>(y, g3, be3, y2_h, y2_l);

    // ---- out = y2 @ W_vr^T + b_vr + template  (direct, S=1) ----
    gemm_b<4><<<dim3((V3DIM+255)/256, 4, 1), 256, BSM_BYTES>>>(
        y2_h, y2_l, Wvr_h, Wvr_l, b_vr, nullptr, tmpl,
        out, nullptr, nullptr, part, cnt, M, V3DIM, DMODEL, 32, 1);
}

// round 13
// speedup vs baseline: 1.9365x; 1.9365x over previous
#include <cuda_runtime.h>
#include <cuda_bf16.h>
#include <math.h>
#include <stdint.h>

typedef __nv_bfloat16 bf16;

// ---------------- problem constants ----------------
#define DMODEL 1024
#define NHEAD  4
#define HDIM   256
#define TLEN   512
#define V3DIM  15069
#define KVPAD  15104
#define DFFDIM 2048
#define AUDDIM 768

// ---------------- fp32 scratch ----------------
__device__ float g_style [DMODEL];
__device__ float g_x     [TLEN * DMODEL];
__device__ float g_y     [TLEN * DMODEL];
__device__ float g_qkv   [TLEN * 3 * DMODEL];
__device__ float g_part  [12 * TLEN * DMODEL];

// ---------------- bf16 hi/lo buffers ----------------
__device__ bf16 g_Waf_h [DMODEL * AUDDIM],  g_Waf_l [DMODEL * AUDDIM];
__device__ bf16 g_Wvm_h [DMODEL * KVPAD],   g_Wvm_l [DMODEL * KVPAD];
__device__ bf16 g_Wqkv_h[3 * DMODEL * DMODEL], g_Wqkv_l[3 * DMODEL * DMODEL];
__device__ bf16 g_Wosa_h[DMODEL * DMODEL],  g_Wosa_l[DMODEL * DMODEL];
__device__ bf16 g_Wvca_h[DMODEL * DMODEL],  g_Wvca_l[DMODEL * DMODEL];
__device__ bf16 g_Woca_h[DMODEL * DMODEL],  g_Woca_l[DMODEL * DMODEL];
__device__ bf16 g_W1_h  [DFFDIM * DMODEL],  g_W1_l  [DFFDIM * DMODEL];
__device__ bf16 g_W2_h  [DMODEL * DFFDIM],  g_W2_l  [DMODEL * DFFDIM];
__device__ bf16 g_Wvr_h [V3DIM * DMODEL],   g_Wvr_l [V3DIM * DMODEL];

__device__ bf16 g_aud_h [TLEN * AUDDIM],  g_aud_l [TLEN * AUDDIM];
__device__ bf16 g_vin_h [TLEN * KVPAD],   g_vin_l [TLEN * KVPAD];
__device__ bf16 g_hid_h [TLEN * DMODEL],  g_hid_l [TLEN * DMODEL];
__device__ bf16 g_xa_h  [TLEN * DMODEL],  g_xa_l  [TLEN * DMODEL];
__device__ bf16 g_x2_h  [TLEN * DMODEL],  g_x2_l  [TLEN * DMODEL];
__device__ bf16 g_y2_h  [TLEN * DMODEL],  g_y2_l  [TLEN * DMODEL];
__device__ bf16 g_attn_h[TLEN * DMODEL],  g_attn_l[TLEN * DMODEL];
__device__ bf16 g_vca_h [TLEN * DMODEL],  g_vca_l [TLEN * DMODEL];
__device__ bf16 g_ff_h  [TLEN * DFFDIM],  g_ff_l  [TLEN * DFFDIM];

// ---------------- helpers ----------------
__device__ __forceinline__ uint32_t smem_u32(const void* p){
    uint32_t a;
    asm("{ .reg .u64 t; cvta.to.shared.u64 t, %1; cvt.u32.u64 %0, t; }" : "=r"(a) : "l"(p));
    return a;
}
__device__ __forceinline__ void cp_async16(uint32_t dst, const void* src, uint32_t sz){
    asm volatile("cp.async.cg.shared.global [%0], [%1], 16, %2;" :: "r"(dst), "l"(src), "r"(sz));
}
__device__ __forceinline__ void cp_commit(){
    asm volatile("cp.async.commit_group;" ::: "memory");
}
__device__ __forceinline__ void cp_wait(int allow){
    if (allow <= 0)      asm volatile("cp.async.wait_group 0;" ::: "memory");
    else                 asm volatile("cp.async.wait_group 1;" ::: "memory");
}
__device__ __forceinline__ void split_write(bf16* hi, bf16* lo, size_t o, float v){
    bf16 h = __float2bfloat16(v);
    hi[o] = h;
    lo[o] = __float2bfloat16(v - __bfloat162float(h));
}
__device__ __forceinline__ uint32_t pk2(float a, float b){
    __nv_bfloat162 t(__float2bfloat16(a), __float2bfloat16(b));
    uint32_t u; memcpy(&u, &t, 4); return u;
}

// ---------------- epilogue ----------------
// EM: 0=+bias ; 1=+bias,relu ; 2=+bias,+resid ; 3=+bias,+style,+PE ; 4=+bias,+template[n]
template<int EM>
__device__ __forceinline__ float apply_epi(float v, int gm, int gn,
    const float* bias, const float* resid, const float* e_aux, int N)
{
    v += bias[gn];
    if (EM == 1) v = fmaxf(v, 0.0f);
    if (EM == 2) v += resid[(size_t)gm * N + gn];
    if (EM == 3) {
        v += e_aux[gn];
        int   p   = gm % 25;
        int   e   = gn & ~1;
        float dv  = expf((float)e * (-9.210340371976184f / 1024.0f));
        float ang = (float)p * dv;
        v += (gn & 1) ? cosf(ang) : sinf(ang);
    }
    if (EM == 4) v += e_aux[gn];
    return v;
}

// ---------------- merged conversion kernel ----------------
#define NJOBS 11
struct ConvJobs {
    const float* src[NJOBS];
    bf16* hi[NJOBS];
    bf16* lo[NJOBS];
    int   K[NJOBS];
    int   Kpad[NJOBS];
    int   mode[NJOBS];      // 0 = plain pad, 1 = vin (shift + subtract tmpl)
    int   blk_end[NJOBS];   // exclusive prefix of block counts
    const float* tmpl;
};

__global__ void __launch_bounds__(256) conv_all(ConvJobs J)
{
    int b = blockIdx.x;
    int j = 0;
#pragma unroll
    for (int t = 0; t < NJOBS; t++) if (b >= J.blk_end[t]) j = t + 1;
    int b0   = (j == 0) ? 0 : J.blk_end[j - 1];
    long e   = (long)(b - b0) * 1024 + threadIdx.x * 4;
    int Kpad = J.Kpad[j], K = J.K[j];
    int row  = (int)(e / Kpad);
    int kp   = (int)(e - (long)row * Kpad);
    const float* src = J.src[j];

    float v[4];
    if (J.mode[j] == 1) {
        if (row == 0) { v[0] = v[1] = v[2] = v[3] = 0.0f; }
        else {
            const float* s = src + (size_t)(row - 1) * K;
#pragma unroll
            for (int i = 0; i < 4; i++) {
                int k = kp + i;
                v[i] = (k < K) ? s[k] - J.tmpl[k] : 0.0f;
            }
        }
    } else {
        const float* s = src + (size_t)row * K;
#pragma unroll
        for (int i = 0; i < 4; i++) {
            int k = kp + i;
            v[i] = (k < K) ? s[k] : 0.0f;
        }
    }
    float h0 = __bfloat162float(__float2bfloat16(v[0]));
    float h1 = __bfloat162float(__float2bfloat16(v[1]));
    float h2 = __bfloat162float(__float2bfloat16(v[2]));
    float h3 = __bfloat162float(__float2bfloat16(v[3]));
    size_t o = (size_t)row * Kpad + kp;
    *(uint2*)(J.hi[j] + o) = make_uint2(pk2(h0, h1), pk2(h2, h3));
    *(uint2*)(J.lo[j] + o) = make_uint2(pk2(v[0] - h0, v[1] - h1),
                                        pk2(v[2] - h2, v[3] - h3));
}

// ---------------- mma.sync GEMM (R5 champion: 2-stage, 2 CTA/SM, 8 warps) ----------------
__device__ __forceinline__ void mma16816(float* c,
    uint32_t a0, uint32_t a1, uint32_t a2, uint32_t a3,
    uint32_t b0, uint32_t b1)
{
    asm volatile("mma.sync.aligned.m16n8k16.row.col.f32.bf16.bf16.f32 "
        "{%0,%1,%2,%3}, {%4,%5,%6,%7}, {%8,%9}, {%0,%1,%2,%3};"
        : "+f"(c[0]), "+f"(c[1]), "+f"(c[2]), "+f"(c[3])
        : "r"(a0), "r"(a1), "r"(a2), "r"(a3), "r"(b0), "r"(b1));
}

#define ROWB    80
#define TILE_SM (128 * ROWB)
#define STG_SM  (4 * TILE_SM)              // 40960 B
#define NSTAGE  2
#define GEMM_SMEM_BYTES (NSTAGE * STG_SM)  // 81920 B -> 2 CTAs/SM

__device__ __forceinline__ void compute_chunk(const char* base, int wm, int wn,
                                              int lane, float (&acc)[4][4][4])
{
    const char* sAh = base;
    const char* sAl = base + TILE_SM;
    const char* sBh = base + 2 * TILE_SM;
    const char* sBl = base + 3 * TILE_SM;
    int l4 = lane >> 2, lt = (lane & 3) * 4;

#pragma unroll
    for (int ks = 0; ks < 2; ks++) {
        int kb = ks * 32 + lt;
        uint32_t bh[4][2], bl[4][2];
#pragma unroll
        for (int nt = 0; nt < 4; nt++) {
            int nr = wn * 32 + nt * 8 + l4;
            const char* p = sBh + nr * ROWB + kb;
            bh[nt][0] = *(const uint32_t*)p;
            bh[nt][1] = *(const uint32_t*)(p + 16);
            const char* q = sBl + nr * ROWB + kb;
            bl[nt][0] = *(const uint32_t*)q;
            bl[nt][1] = *(const uint32_t*)(q + 16);
        }
#pragma unroll
        for (int mt = 0; mt < 4; mt++) {
            int r0 = wm * 64 + mt * 16 + l4;
            const char* p = sAh + r0 * ROWB + kb;
            uint32_t ah0 = *(const uint32_t*)p;
            uint32_t ah1 = *(const uint32_t*)(p + 8 * ROWB);
            uint32_t ah2 = *(const uint32_t*)(p + 16);
            uint32_t ah3 = *(const uint32_t*)(p + 8 * ROWB + 16);
            const char* q = sAl + r0 * ROWB + kb;
            uint32_t al0 = *(const uint32_t*)q;
            uint32_t al1 = *(const uint32_t*)(q + 8 * ROWB);
            uint32_t al2 = *(const uint32_t*)(q + 16);
            uint32_t al3 = *(const uint32_t*)(q + 8 * ROWB + 16);
#pragma unroll
            for (int nt = 0; nt < 4; nt++)
                mma16816(acc[mt][nt], ah0, ah1, ah2, ah3, bh[nt][0], bh[nt][1]);
#pragma unroll
            for (int nt = 0; nt < 4; nt++)
                mma16816(acc[mt][nt], ah0, ah1, ah2, ah3, bl[nt][0], bl[nt][1]);
#pragma unroll
            for (int nt = 0; nt < 4; nt++)
                mma16816(acc[mt][nt], al0, al1, al2, al3, bh[nt][0], bh[nt][1]);
        }
    }
}

__device__ __forceinline__ void stage_copy(uint32_t sb32, int stage,
    const bf16* __restrict__ Ah, const bf16* __restrict__ Al,
    const bf16* __restrict__ Bh, const bf16* __restrict__ Bl,
    int bm, int bn, int N, int Kpad, int kk, int tid)
{
    uint32_t st = sb32 + stage * STG_SM;
#pragma unroll
    for (int c = 0; c < 8; c++) {
        int g    = c * 256 + tid;
        int tile = g >> 9;
        int rem  = g & 511;
        int row  = rem >> 2, col = rem & 3;
        uint32_t dst = st + tile * TILE_SM + row * ROWB + col * 16;
        const bf16* base;
        int rowg; uint32_t sz = 16;
        if (tile < 2) { base = tile ? Al : Ah; rowg = bm + row; }
        else {
            base = (tile == 3) ? Bl : Bh; rowg = bn + row;
            if (rowg >= N) { rowg = 0; sz = 0; }
        }
        cp_async16(dst, base + (size_t)rowg * Kpad + kk + col * 8, sz);
    }
}

template<int EM>
__global__ void __launch_bounds__(256, 2) mma_gemm2(
    const bf16* __restrict__ Ah, const bf16* __restrict__ Al,
    const bf16* __restrict__ Bh, const bf16* __restrict__ Bl,
    const float* __restrict__ bias, const float* __restrict__ e_aux,
    float* __restrict__ C, float* __restrict__ Cpart,
    int M, int N, int Kpad, int nchunks, int nsplit)
{
    extern __shared__ __align__(16) char smem[];
    uint32_t sb32 = smem_u32(smem);
    int tid  = threadIdx.x;
    int wid  = tid >> 5, lane = tid & 31;
    int wm   = wid >> 2, wn = wid & 3;
    int bm   = blockIdx.y * 128, bn = blockIdx.x * 128;
    int cpz  = (nchunks + nsplit - 1) / nsplit;
    int c0   = blockIdx.z * cpz;
    int c1   = min(nchunks, c0 + cpz);
    int nloc = c1 - c0;

    float acc[4][4][4];
#pragma unroll
    for (int a = 0; a < 4; a++)
#pragma unroll
        for (int b = 0; b < 4; b++)
#pragma unroll
            for (int c = 0; c < 4; c++) acc[a][b][c] = 0.0f;

    int npre = min(NSTAGE, nloc);
    for (int s = 0; s < npre; s++) {
        stage_copy(sb32, s, Ah, Al, Bh, Bl, bm, bn, N, Kpad, (c0 + s) * 32, tid);
        cp_commit();
    }

    for (int j = 0; j < nloc; j++) {
        cp_wait(min(nloc - 1 - j, NSTAGE - 1));
        __syncthreads();
        compute_chunk(smem + (j % NSTAGE) * STG_SM, wm, wn, lane, acc);
        __syncthreads();
        if (j + NSTAGE < nloc) {
            stage_copy(sb32, j % NSTAGE, Ah, Al, Bh, Bl, bm, bn, N, Kpad,
                       (c0 + j + NSTAGE) * 32, tid);
            cp_commit();
        }
    }

    int l4 = lane >> 2, lt = lane & 3;
#pragma unroll
    for (int mt = 0; mt < 4; mt++) {
#pragma unroll
        for (int nt = 0; nt < 4; nt++) {
            int r0 = bm + wm * 64 + mt * 16 + l4;
            int cc = bn + wn * 32 + nt * 8 + lt * 2;
            float* a4 = acc[mt][nt];
            if (nsplit == 1) {
                if (cc < N) {
                    C[(size_t)r0 * N + cc]       = apply_epi<EM>(a4[0], r0, cc, bias, nullptr, e_aux, N);
                    C[(size_t)(r0 + 8) * N + cc] = apply_epi<EM>(a4[2], r0 + 8, cc, bias, nullptr, e_aux, N);
                }
                if (cc + 1 < N) {
                    C[(size_t)r0 * N + cc + 1]       = apply_epi<EM>(a4[1], r0, cc + 1, bias, nullptr, e_aux, N);
                    C[(size_t)(r0 + 8) * N + cc + 1] = apply_epi<EM>(a4[3], r0 + 8, cc + 1, bias, nullptr, e_aux, N);
                }
            } else {
                float* P = Cpart + (size_t)blockIdx.z * M * N;
                if (cc < N) {
                    P[(size_t)r0 * N + cc]       = a4[0];
                    P[(size_t)(r0 + 8) * N + cc] = a4[2];
                }
                if (cc + 1 < N) {
                    P[(size_t)r0 * N + cc + 1]       = a4[1];
                    P[(size_t)(r0 + 8) * N + cc + 1] = a4[3];
                }
            }
        }
    }
}

// ---------------- split-K reduction + epilogue (float4, 4 elems/thread) ----------------
template<int EM>
__global__ void reduce_epi(const float* __restrict__ Cpart,
    const float* __restrict__ bias, const float* __restrict__ resid,
    const float* __restrict__ e_aux, float* __restrict__ C,
    bf16* __restrict__ Chi, bf16* __restrict__ Clo, int M, int N, int S)
{
    int idx4 = (blockIdx.x * 256 + threadIdx.x) * 4;
    if (idx4 >= M * N) return;
    float4 s = make_float4(0.f, 0.f, 0.f, 0.f);
    for (int z = 0; z < S; z++) {
        float4 p = *(const float4*)(Cpart + (size_t)z * M * N + idx4);
        s.x += p.x; s.y += p.y; s.z += p.z; s.w += p.w;
    }
    int gm = idx4 / N, gn = idx4 - gm * N;      // N % 4 == 0 -> no row split
    float v0 = apply_epi<EM>(s.x, gm, gn,     bias, resid, e_aux, N);
    float v1 = apply_epi<EM>(s.y, gm, gn + 1, bias, resid, e_aux, N);
    float v2 = apply_epi<EM>(s.z, gm, gn + 2, bias, resid, e_aux, N);
    float v3 = apply_epi<EM>(s.w, gm, gn + 3, bias, resid, e_aux, N);
    if (C) *(float4*)(C + idx4) = make_float4(v0, v1, v2, v3);
    if (Chi) {
        *(uint2*)(Chi + idx4) = make_uint2(pk2(v0, v1), pk2(v2, v3));
        float h0 = __bfloat162float(__float2bfloat16(v0));
        float h1 = __bfloat162float(__float2bfloat16(v1));
        float h2 = __bfloat162float(__float2bfloat16(v2));
        float h3 = __bfloat162float(__float2bfloat16(v3));
        *(uint2*)(Clo + idx4) = make_uint2(pk2(v0 - h0, v1 - h1), pk2(v2 - h2, v3 - h3));
    }
}

// ---------------- style ----------------
__global__ void style_k(const float* __restrict__ oh, const float* __restrict__ W,
                        float* __restrict__ st)
{
    int d = blockIdx.x * blockDim.x + threadIdx.x;
    if (d < DMODEL) {
        float s = 0.0f;
#pragma unroll
        for (int n = 0; n < 8; n++) s += oh[n] * W[d * 8 + n];
        st[d] = s;
    }
}

// ---------------- LayerNorm ----------------
__device__ __forceinline__ float block_sum(float v, float* sred)
{
    __syncthreads();
#pragma unroll
    for (int o = 16; o; o >>= 1) v += __shfl_xor_sync(0xffffffffu, v, o);
    int w = threadIdx.x >> 5, l = threadIdx.x & 31;
    if (l == 0) sred[w] = v;
    __syncthreads();
    float t = (l < 8) ? sred[l] : 0.0f;
#pragma unroll
    for (int o = 4; o; o >>= 1) t += __shfl_xor_sync(0xffffffffu, t, o);
    if (threadIdx.x == 0) sred[0] = t;
    __syncthreads();
    return sred[0];
}

__global__ void __launch_bounds__(256) layernorm_k(float* __restrict__ x,
    const float* __restrict__ g, const float* __restrict__ b,
    bf16* __restrict__ hi, bf16* __restrict__ lo)
{
    __shared__ float sred[32];
    int row = blockIdx.x, tid = threadIdx.x;
    float v[4];
    float s = 0.0f;
#pragma unroll
    for (int i = 0; i < 4; i++) { v[i] = x[row * DMODEL + i * 256 + tid]; s += v[i]; }
    float mean = block_sum(s, sred) * (1.0f / 1024.0f);
    float sq = 0.0f;
#pragma unroll
    for (int i = 0; i < 4; i++) { float d = v[i] - mean; sq += d * d; }
    float var  = block_sum(sq, sred) * (1.0f / 1024.0f);
    float rstd = rsqrtf(var + 1e-5f);
#pragma unroll
    for (int i = 0; i < 4; i++) {
        int c = i * 256 + tid;
        float o = (v[i] - mean) * rstd * g[c] + b[c];
        x[row * DMODEL + c] = o;
        if (hi) split_write(hi, lo, (size_t)row * DMODEL + c, o);
    }
}

// ---------------- fused self-attention ----------------
#define ATT_BQ 16
#define ATT_KT 64
#define SPAD   516
#define QS_FLOATS (256 * 17)
#define SS_FLOATS (ATT_BQ * SPAD)
#define KV_FLOATS (256 * 68)
#define ATT_SMEM_BYTES ((QS_FLOATS + SS_FLOATS + KV_FLOATS) * 4)

__global__ void __launch_bounds__(256) attention_sa(const float* __restrict__ qkv,
                                                    bf16* __restrict__ ohi,
                                                    bf16* __restrict__ olo)
{
    extern __shared__ __align__(16) float sm[];
    float* Qs = sm;
    float* Ss = sm + QS_FLOATS;
    float* KV = sm + QS_FLOATS + SS_FLOATS;

    int h   = blockIdx.y;
    int q0  = blockIdx.x * ATT_BQ;
    int tid = threadIdx.x;
    float slope = exp2f(-2.0f * (float)(h + 1));

    for (int idx = tid; idx < ATT_BQ * 256; idx += 256) {
        int qi = idx >> 8, d = idx & 255;
        Qs[d * 17 + qi] = qkv[(size_t)(q0 + qi) * 3072 + h * 256 + d];
    }
    __syncthreads();

    int qmax = q0 + ATT_BQ - 1;
    int qi   = tid >> 4;

    {
        int kk0 = (tid & 15) * 4;
        for (int s0 = 0; s0 < TLEN; s0 += ATT_KT) {
            if (s0 > qmax) {
                for (int idx = tid; idx < ATT_BQ * ATT_KT; idx += 256) {
                    int rr = idx >> 6, cc = idx & 63;
                    Ss[rr * SPAD + s0 + cc] = -1e30f;
                }
                continue;
            }
            for (int idx = tid; idx < ATT_KT * 256; idx += 256) {
                int kk = idx >> 8, d = idx & 255;
                KV[d * 68 + kk] = qkv[(size_t)(s0 + kk) * 3072 + 1024 + h * 256 + d];
            }
            __syncthreads();
            float a0 = 0.f, a1 = 0.f, a2 = 0.f, a3 = 0.f;
#pragma unroll 4
            for (int d = 0; d < 256; d++) {
                float  qv = Qs[d * 17 + qi];
                float4 kv = *(const float4*)&KV[d * 68 + kk0];
                a0 = fmaf(qv, kv.x, a0);
                a1 = fmaf(qv, kv.y, a1);
                a2 = fmaf(qv, kv.z, a2);
                a3 = fmaf(qv, kv.w, a3);
            }
            int i  = q0 + qi;
            int jb = s0 + kk0;
            float accs[4] = {a0, a1, a2, a3};
#pragma unroll
            for (int c = 0; c < 4; c++) {
                int jj = jb + c;
                float mv = (jj > i) ? -1e30f : (-slope * (float)((i - jj) / 25));
                Ss[qi * SPAD + jj] = accs[c] * 0.0625f + mv;
            }
            __syncthreads();
        }
    }
    __syncthreads();

    {
        int warp = tid >> 5, lane = tid & 31;
        for (int rr = warp; rr < ATT_BQ; rr += 8) {
            float mx = -1e30f;
            for (int jj = lane; jj < TLEN; jj += 32) mx = fmaxf(mx, Ss[rr * SPAD + jj]);
#pragma unroll
            for (int o = 16; o; o >>= 1) mx = fmaxf(mx, __shfl_xor_sync(0xffffffffu, mx, o));
            float sum = 0.0f;
            for (int jj = lane; jj < TLEN; jj += 32) {
                float e = expf(Ss[rr * SPAD + jj] - mx);
                Ss[rr * SPAD + jj] = e;
                sum += e;
            }
#pragma unroll
            for (int o = 16; o; o >>= 1) sum += __shfl_xor_sync(0xffffffffu, sum, o);
            float inv = 1.0f / sum;
            for (int jj = lane; jj < TLEN; jj += 32) Ss[rr * SPAD + jj] *= inv;
        }
    }
    __syncthreads();

    float acc[16];
#pragma unroll
    for (int i = 0; i < 16; i++) acc[i] = 0.0f;
    int d0 = (tid & 15) * 16;

    for (int s0 = 0; s0 <= qmax; s0 += ATT_KT) {
        for (int idx = tid; idx < ATT_KT * 256; idx += 256) {
            int kk = idx >> 8, d = idx & 255;
            KV[kk * 256 + d] = qkv[(size_t)(s0 + kk) * 3072 + 2048 + h * 256 + d];
        }
        __syncthreads();
        for (int kk = 0; kk < ATT_KT; kk++) {
            float a = Ss[qi * SPAD + s0 + kk];
            const float4* vp = (const float4*)&KV[kk * 256 + d0];
            float4 v0 = vp[0], v1 = vp[1], v2 = vp[2], v3 = vp[3];
            acc[0]  = fmaf(a, v0.x, acc[0]);  acc[1]  = fmaf(a, v0.y, acc[1]);
            acc[2]  = fmaf(a, v0.z, acc[2]);  acc[3]  = fmaf(a, v0.w, acc[3]);
            acc[4]  = fmaf(a, v1.x, acc[4]);  acc[5]  = fmaf(a, v1.y, acc[5]);
            acc[6]  = fmaf(a, v1.z, acc[6]);  acc[7]  = fmaf(a, v1.w, acc[7]);
            acc[8]  = fmaf(a, v2.x, acc[8]);  acc[9]  = fmaf(a, v2.y, acc[9]);
            acc[10] = fmaf(a, v2.z, acc[10]); acc[11] = fmaf(a, v2.w, acc[11]);
            acc[12] = fmaf(a, v3.x, acc[12]); acc[13] = fmaf(a, v3.y, acc[13]);
            acc[14] = fmaf(a, v3.z, acc[14]); acc[15] = fmaf(a, v3.w, acc[15]);
        }
        __syncthreads();
    }
#pragma unroll
    for (int c = 0; c < 16; c++)
        split_write(ohi, olo, (size_t)(q0 + qi) * 1024 + h * 256 + d0 + c, acc[c]);
}

// ---------------- launcher ----------------
extern "C" void kernel_launch(void* const* d_in, const int* in_sizes, int n_in,
                              void* d_out, int out_size)
{
    const float* audio   = (const float*)d_in[0];
    const float* vertice = (const float*)d_in[1];
    const float* tmpl    = (const float*)d_in[2];
    const float* one_hot = (const float*)d_in[3];
    const float* W_af    = (const float*)d_in[4];
    const float* b_af    = (const float*)d_in[5];
    const float* W_vm    = (const float*)d_in[6];
    const float* b_vm    = (const float*)d_in[7];
    const float* W_obj   = (const float*)d_in[8];
    const float* Wqkv_sa = (const float*)d_in[9];
    const float* bqkv_sa = (const float*)d_in[10];
    const float* Wo_sa   = (const float*)d_in[11];
    const float* bo_sa   = (const float*)d_in[12];
    const float* Wqkv_ca = (const float*)d_in[13];
    const float* bqkv_ca = (const float*)d_in[14];
    const float* Wo_ca   = (const float*)d_in[15];
    const float* bo_ca   = (const float*)d_in[16];
    const float* W1      = (const float*)d_in[17];
    const float* b1      = (const float*)d_in[18];
    const float* W2      = (const float*)d_in[19];
    const float* b2      = (const float*)d_in[20];
    const float* g1      = (const float*)d_in[21];
    const float* be1     = (const float*)d_in[22];
    const float* g2      = (const float*)d_in[23];
    const float* be2     = (const float*)d_in[24];
    const float* g3      = (const float*)d_in[25];
    const float* be3     = (const float*)d_in[26];
    const float* W_vr    = (const float*)d_in[27];
    const float* b_vr    = (const float*)d_in[28];
    float* out = (float*)d_out;

    float *style, *x, *y, *qkv, *part;
    cudaGetSymbolAddress((void**)&style, g_style);
    cudaGetSymbolAddress((void**)&x,     g_x);
    cudaGetSymbolAddress((void**)&y,     g_y);
    cudaGetSymbolAddress((void**)&qkv,   g_qkv);
    cudaGetSymbolAddress((void**)&part,  g_part);

#define SYM(p, s) bf16* p; cudaGetSymbolAddress((void**)&p, s)
    SYM(Waf_h, g_Waf_h);  SYM(Waf_l, g_Waf_l);
    SYM(Wvm_h, g_Wvm_h);  SYM(Wvm_l, g_Wvm_l);
    SYM(Wqkv_h, g_Wqkv_h); SYM(Wqkv_l, g_Wqkv_l);
    SYM(Wosa_h, g_Wosa_h); SYM(Wosa_l, g_Wosa_l);
    SYM(Wvca_h, g_Wvca_h); SYM(Wvca_l, g_Wvca_l);
    SYM(Woca_h, g_Woca_h); SYM(Woca_l, g_Woca_l);
    SYM(W1_h, g_W1_h);    SYM(W1_l, g_W1_l);
    SYM(W2_h, g_W2_h);    SYM(W2_l, g_W2_l);
    SYM(Wvr_h, g_Wvr_h);  SYM(Wvr_l, g_Wvr_l);
    SYM(aud_h, g_aud_h);  SYM(aud_l, g_aud_l);
    SYM(vin_h, g_vin_h);  SYM(vin_l, g_vin_l);
    SYM(hid_h, g_hid_h);  SYM(hid_l, g_hid_l);
    SYM(xa_h, g_xa_h);    SYM(xa_l, g_xa_l);
    SYM(x2_h, g_x2_h);    SYM(x2_l, g_x2_l);
    SYM(y2_h, g_y2_h);    SYM(y2_l, g_y2_l);
    SYM(attn_h, g_attn_h); SYM(attn_l, g_attn_l);
    SYM(vca_h, g_vca_h);  SYM(vca_l, g_vca_l);
    SYM(ff_h, g_ff_h);    SYM(ff_l, g_ff_l);
#undef SYM

    cudaFuncSetAttribute(attention_sa,
        cudaFuncAttributeMaxDynamicSharedMemorySize, ATT_SMEM_BYTES);
    cudaFuncSetAttribute(mma_gemm2<0>,
        cudaFuncAttributeMaxDynamicSharedMemorySize, GEMM_SMEM_BYTES);
    cudaFuncSetAttribute(mma_gemm2<4>,
        cudaFuncAttributeMaxDynamicSharedMemorySize, GEMM_SMEM_BYTES);

    const int M = TLEN;

    // ---- single merged conversion launch ----
    {
        ConvJobs J;
        J.tmpl = tmpl;
        const float* srcs[NJOBS] = { W_af, audio, W_vm, vertice, Wqkv_sa,
                                     Wo_sa, Wqkv_ca + (size_t)2048*DMODEL, Wo_ca,
                                     W1, W2, W_vr };
        bf16* his[NJOBS] = { Waf_h, aud_h, Wvm_h, vin_h, Wqkv_h, Wosa_h, Wvca_h,
                             Woca_h, W1_h, W2_h, Wvr_h };
        bf16* los[NJOBS] = { Waf_l, aud_l, Wvm_l, vin_l, Wqkv_l, Wosa_l, Wvca_l,
                             Woca_l, W1_l, W2_l, Wvr_l };
        int Ks[NJOBS]    = { AUDDIM, AUDDIM, V3DIM, V3DIM, DMODEL, DMODEL, DMODEL,
                             DMODEL, DMODEL, DFFDIM, DMODEL };
        int Kps[NJOBS]   = { AUDDIM, AUDDIM, KVPAD, KVPAD, DMODEL, DMODEL, DMODEL,
                             DMODEL, DMODEL, DFFDIM, DMODEL };
        int rows[NJOBS]  = { DMODEL, TLEN, DMODEL, TLEN, 3*DMODEL, DMODEL, DMODEL,
                             DMODEL, DFFDIM, DMODEL, V3DIM };
        int modes[NJOBS] = { 0, 0, 0, 1, 0, 0, 0, 0, 0, 0, 0 };
        int nb = 0;
        for (int t = 0; t < NJOBS; t++) {
            J.src[t] = srcs[t]; J.hi[t] = his[t]; J.lo[t] = los[t];
            J.K[t] = Ks[t]; J.Kpad[t] = Kps[t]; J.mode[t] = modes[t];
            nb += (int)(((long)rows[t] * Kps[t] + 1023) / 1024);
            J.blk_end[t] = nb;
        }
        conv_all<<<nb, 256>>>(J);
    }
    style_k<<<4, 256>>>(one_hot, W_obj, style);

    // ---- hidden = audio @ W_af^T + b_af  (K=768: 24 chunks, split 4) ----
    mma_gemm2<0><<<dim3(8,4,4), 256, GEMM_SMEM_BYTES>>>(
        aud_h, aud_l, Waf_h, Waf_l, nullptr, nullptr,
        nullptr, part, M, DMODEL, AUDDIM, 24, 4);
    reduce_epi<0><<<(M*DMODEL/4+255)/256, 256>>>(part, b_af, nullptr, nullptr,
        nullptr, hid_h, hid_l, M, DMODEL, 4);

    // ---- x = vin @ W_vm^T + b_vm + style + PE  (472 chunks, split 9) ----
    mma_gemm2<0><<<dim3(8,4,9), 256, GEMM_SMEM_BYTES>>>(
        vin_h, vin_l, Wvm_h, Wvm_l, nullptr, nullptr,
        nullptr, part, M, DMODEL, KVPAD, 472, 9);
    reduce_epi<3><<<(M*DMODEL/4+255)/256, 256>>>(part, b_vm, nullptr, style,
        x, xa_h, xa_l, M, DMODEL, 9);

    // ---- qkv = xa @ Wqkv^T + bqkv  (N=3072, split 2) ----
    mma_gemm2<0><<<dim3(24,4,2), 256, GEMM_SMEM_BYTES>>>(
        xa_h, xa_l, Wqkv_h, Wqkv_l, nullptr, nullptr,
        nullptr, part, M, 3*DMODEL, DMODEL, 32, 2);
    reduce_epi<0><<<(M*3*DMODEL/4+255)/256, 256>>>(part, bqkv_sa, nullptr, nullptr,
        qkv, nullptr, nullptr, M, 3*DMODEL, 2);

    attention_sa<<<dim3(TLEN/ATT_BQ, NHEAD), 256, ATT_SMEM_BYTES>>>(qkv, attn_h, attn_l);

    // ---- y = x + attn @ Wo_sa^T + bo_sa ; LN1 ----
    mma_gemm2<0><<<dim3(8,4,4), 256, GEMM_SMEM_BYTES>>>(
        attn_h, attn_l, Wosa_h, Wosa_l, nullptr, nullptr,
        nullptr, part, M, DMODEL, DMODEL, 32, 4);
    reduce_epi<2><<<(M*DMODEL/4+255)/256, 256>>>(part, bo_sa, x, nullptr,
        y, nullptr, nullptr, M, DMODEL, 4);
    layernorm_k<<<M, 256>>>(y, g1, be1, nullptr, nullptr);

    // ---- cross-attn (diagonal) ----
    mma_gemm2<0><<<dim3(8,4,4), 256, GEMM_SMEM_BYTES>>>(
        hid_h, hid_l, Wvca_h, Wvca_l, nullptr, nullptr,
        nullptr, part, M, DMODEL, DMODEL, 32, 4);
    reduce_epi<0><<<(M*DMODEL/4+255)/256, 256>>>(part, bqkv_ca + 2048, nullptr, nullptr,
        nullptr, vca_h, vca_l, M, DMODEL, 4);
    mma_gemm2<0><<<dim3(8,4,4), 256, GEMM_SMEM_BYTES>>>(
        vca_h, vca_l, Woca_h, Woca_l, nullptr, nullptr,
        nullptr, part, M, DMODEL, DMODEL, 32, 4);
    reduce_epi<2><<<(M*DMODEL/4+255)/256, 256>>>(part, bo_ca, y, nullptr,
        x, nullptr, nullptr, M, DMODEL, 4);
    layernorm_k<<<M, 256>>>(x, g2, be2, x2_h, x2_l);

    // ---- FFN ----
    mma_gemm2<0><<<dim3(16,4,2), 256, GEMM_SMEM_BYTES>>>(
        x2_h, x2_l, W1_h, W1_l, nullptr, nullptr,
        nullptr, part, M, DFFDIM, DMODEL, 32, 2);
    reduce_epi<1><<<(M*DFFDIM/4+255)/256, 256>>>(part, b1, nullptr, nullptr,
        nullptr, ff_h, ff_l, M, DFFDIM, 2);
    mma_gemm2<0><<<dim3(8,4,4), 256, GEMM_SMEM_BYTES>>>(
        ff_h, ff_l, W2_h, W2_l, nullptr, nullptr,
        nullptr, part, M, DMODEL, DFFDIM, 64, 4);
    reduce_epi<2><<<(M*DMODEL/4+255)/256, 256>>>(part, b2, x, nullptr,
        y, nullptr, nullptr, M, DMODEL, 4);
    layernorm_k<<<M, 256>>>(y, g3, be3, y2_h, y2_l);

    // ---- out = y @ W_vr^T + b_vr + template ----
    mma_gemm2<4><<<dim3((V3DIM+127)/128, 4, 1), 256, GEMM_SMEM_BYTES>>>(
        y2_h, y2_l, Wvr_h, Wvr_l, b_vr, tmpl,
        out, nullptr, M, V3DIM, DMODEL, 32, 1);
}

// round 14
// speedup vs baseline: 1.9457x; 1.0047x over previous
#include <cuda_runtime.h>
#include <cuda_bf16.h>
#include <math.h>
#include <stdint.h>

typedef __nv_bfloat16 bf16;

// ---------------- problem constants ----------------
#define DMODEL 1024
#define NHEAD  4
#define HDIM   256
#define TLEN   512
#define V3DIM  15069
#define KVPAD  15104
#define DFFDIM 2048
#define AUDDIM 768

// ---------------- fp32 scratch ----------------
__device__ float g_style [DMODEL];
__device__ float g_x     [TLEN * DMODEL];
__device__ float g_y     [TLEN * DMODEL];
__device__ float g_qkv   [TLEN * 3 * DMODEL];
__device__ float g_part  [12 * TLEN * DMODEL];

// ---------------- bf16 hi/lo buffers ----------------
__device__ bf16 g_Waf_h [DMODEL * AUDDIM],  g_Waf_l [DMODEL * AUDDIM];
__device__ bf16 g_Wvm_h [DMODEL * KVPAD],   g_Wvm_l [DMODEL * KVPAD];
__device__ bf16 g_Wqkv_h[3 * DMODEL * DMODEL], g_Wqkv_l[3 * DMODEL * DMODEL];
__device__ bf16 g_Wosa_h[DMODEL * DMODEL],  g_Wosa_l[DMODEL * DMODEL];
__device__ bf16 g_Wvca_h[DMODEL * DMODEL],  g_Wvca_l[DMODEL * DMODEL];
__device__ bf16 g_Woca_h[DMODEL * DMODEL],  g_Woca_l[DMODEL * DMODEL];
__device__ bf16 g_W1_h  [DFFDIM * DMODEL],  g_W1_l  [DFFDIM * DMODEL];
__device__ bf16 g_W2_h  [DMODEL * DFFDIM],  g_W2_l  [DMODEL * DFFDIM];
__device__ bf16 g_Wvr_h [V3DIM * DMODEL],   g_Wvr_l [V3DIM * DMODEL];

__device__ bf16 g_aud_h [TLEN * AUDDIM],  g_aud_l [TLEN * AUDDIM];
__device__ bf16 g_vin_h [TLEN * KVPAD],   g_vin_l [TLEN * KVPAD];
__device__ bf16 g_hid_h [TLEN * DMODEL],  g_hid_l [TLEN * DMODEL];
__device__ bf16 g_xa_h  [TLEN * DMODEL],  g_xa_l  [TLEN * DMODEL];
__device__ bf16 g_x2_h  [TLEN * DMODEL],  g_x2_l  [TLEN * DMODEL];
__device__ bf16 g_y2_h  [TLEN * DMODEL],  g_y2_l  [TLEN * DMODEL];
__device__ bf16 g_attn_h[TLEN * DMODEL],  g_attn_l[TLEN * DMODEL];
__device__ bf16 g_vca_h [TLEN * DMODEL],  g_vca_l [TLEN * DMODEL];
__device__ bf16 g_ff_h  [TLEN * DFFDIM],  g_ff_l  [TLEN * DFFDIM];

// ---------------- helpers ----------------
__device__ __forceinline__ uint32_t smem_u32(const void* p){
    uint32_t a;
    asm("{ .reg .u64 t; cvta.to.shared.u64 t, %1; cvt.u32.u64 %0, t; }" : "=r"(a) : "l"(p));
    return a;
}
__device__ __forceinline__ void cp_async16(uint32_t dst, const void* src, uint32_t sz){
    asm volatile("cp.async.cg.shared.global [%0], [%1], 16, %2;" :: "r"(dst), "l"(src), "r"(sz));
}
__device__ __forceinline__ void cp_commit(){
    asm volatile("cp.async.commit_group;" ::: "memory");
}
__device__ __forceinline__ void cp_wait(int allow){
    if (allow <= 0)      asm volatile("cp.async.wait_group 0;" ::: "memory");
    else                 asm volatile("cp.async.wait_group 1;" ::: "memory");
}
__device__ __forceinline__ void split_write(bf16* hi, bf16* lo, size_t o, float v){
    bf16 h = __float2bfloat16(v);
    hi[o] = h;
    lo[o] = __float2bfloat16(v - __bfloat162float(h));
}
__device__ __forceinline__ uint32_t pk2(float a, float b){
    __nv_bfloat162 t(__float2bfloat16(a), __float2bfloat16(b));
    uint32_t u; memcpy(&u, &t, 4); return u;
}

// ---------------- epilogue ----------------
// EM: 0=+bias ; 1=+bias,relu ; 2=+bias,+resid ; 3=+bias,+style,+PE ; 4=+bias,+template[n]
template<int EM>
__device__ __forceinline__ float apply_epi(float v, int gm, int gn,
    const float* bias, const float* resid, const float* e_aux, int N)
{
    v += bias[gn];
    if (EM == 1) v = fmaxf(v, 0.0f);
    if (EM == 2) v += resid[(size_t)gm * N + gn];
    if (EM == 3) {
        v += e_aux[gn];
        int   p   = gm % 25;
        int   e   = gn & ~1;
        float dv  = expf((float)e * (-9.210340371976184f / 1024.0f));
        float ang = (float)p * dv;
        v += (gn & 1) ? cosf(ang) : sinf(ang);
    }
    if (EM == 4) v += e_aux[gn];
    return v;
}

// ---------------- merged conversion kernel: 16 elems/thread (MLP ~16) ----------------
#define NJOBS 11
struct ConvJobs {
    const float* src[NJOBS];
    bf16* hi[NJOBS];
    bf16* lo[NJOBS];
    int   K[NJOBS];
    int   Kpad[NJOBS];
    long  total[NJOBS];     // rows * Kpad
    int   mode[NJOBS];      // 0 = plain pad, 1 = vin (shift + subtract tmpl)
    int   blk_end[NJOBS];   // exclusive prefix of block counts
    const float* tmpl;
};

__global__ void __launch_bounds__(256) conv_all(ConvJobs J)
{
    int b = blockIdx.x;
    int j = 0;
#pragma unroll
    for (int t = 0; t < NJOBS; t++) if (b >= J.blk_end[t]) j = t + 1;
    int b0    = (j == 0) ? 0 : J.blk_end[j - 1];
    long e0   = (long)(b - b0) * 4096 + threadIdx.x * 4;
    int Kpad  = J.Kpad[j], K = J.K[j];
    long tot  = J.total[j];
    const float* src = J.src[j];
    int mode  = J.mode[j];
    bf16* hi  = J.hi[j];
    bf16* lo  = J.lo[j];

#pragma unroll
    for (int q = 0; q < 4; q++) {
        long e = e0 + q * 1024;            // 256 threads x 4 elems per group
        if (e >= tot) break;
        int row = (int)(e / Kpad);
        int kp  = (int)(e - (long)row * Kpad);
        float v[4];
        if (mode == 1) {
            if (row == 0) { v[0] = v[1] = v[2] = v[3] = 0.0f; }
            else {
                const float* s = src + (size_t)(row - 1) * K;
#pragma unroll
                for (int i = 0; i < 4; i++) {
                    int k = kp + i;
                    v[i] = (k < K) ? s[k] - J.tmpl[k] : 0.0f;
                }
            }
        } else {
            const float* s = src + (size_t)row * K;
#pragma unroll
            for (int i = 0; i < 4; i++) {
                int k = kp + i;
                v[i] = (k < K) ? s[k] : 0.0f;
            }
        }
        float h0 = __bfloat162float(__float2bfloat16(v[0]));
        float h1 = __bfloat162float(__float2bfloat16(v[1]));
        float h2 = __bfloat162float(__float2bfloat16(v[2]));
        float h3 = __bfloat162float(__float2bfloat16(v[3]));
        size_t o = (size_t)row * Kpad + kp;
        *(uint2*)(hi + o) = make_uint2(pk2(h0, h1), pk2(h2, h3));
        *(uint2*)(lo + o) = make_uint2(pk2(v[0] - h0, v[1] - h1),
                                       pk2(v[2] - h2, v[3] - h3));
    }
}

// ---------------- mma.sync GEMM (champion: 2-stage, 2 CTA/SM, 8 warps) ----------------
__device__ __forceinline__ void mma16816(float* c,
    uint32_t a0, uint32_t a1, uint32_t a2, uint32_t a3,
    uint32_t b0, uint32_t b1)
{
    asm volatile("mma.sync.aligned.m16n8k16.row.col.f32.bf16.bf16.f32 "
        "{%0,%1,%2,%3}, {%4,%5,%6,%7}, {%8,%9}, {%0,%1,%2,%3};"
        : "+f"(c[0]), "+f"(c[1]), "+f"(c[2]), "+f"(c[3])
        : "r"(a0), "r"(a1), "r"(a2), "r"(a3), "r"(b0), "r"(b1));
}

#define ROWB    80
#define TILE_SM (128 * ROWB)
#define STG_SM  (4 * TILE_SM)              // 40960 B
#define NSTAGE  2
#define GEMM_SMEM_BYTES (NSTAGE * STG_SM)  // 81920 B -> 2 CTAs/SM

__device__ __forceinline__ void compute_chunk(const char* base, int wm, int wn,
                                              int lane, float (&acc)[4][4][4])
{
    const char* sAh = base;
    const char* sAl = base + TILE_SM;
    const char* sBh = base + 2 * TILE_SM;
    const char* sBl = base + 3 * TILE_SM;
    int l4 = lane >> 2, lt = (lane & 3) * 4;

#pragma unroll
    for (int ks = 0; ks < 2; ks++) {
        int kb = ks * 32 + lt;
        uint32_t bh[4][2], bl[4][2];
#pragma unroll
        for (int nt = 0; nt < 4; nt++) {
            int nr = wn * 32 + nt * 8 + l4;
            const char* p = sBh + nr * ROWB + kb;
            bh[nt][0] = *(const uint32_t*)p;
            bh[nt][1] = *(const uint32_t*)(p + 16);
            const char* q = sBl + nr * ROWB + kb;
            bl[nt][0] = *(const uint32_t*)q;
            bl[nt][1] = *(const uint32_t*)(q + 16);
        }
#pragma unroll
        for (int mt = 0; mt < 4; mt++) {
            int r0 = wm * 64 + mt * 16 + l4;
            const char* p = sAh + r0 * ROWB + kb;
            uint32_t ah0 = *(const uint32_t*)p;
            uint32_t ah1 = *(const uint32_t*)(p + 8 * ROWB);
            uint32_t ah2 = *(const uint32_t*)(p + 16);
            uint32_t ah3 = *(const uint32_t*)(p + 8 * ROWB + 16);
            const char* q = sAl + r0 * ROWB + kb;
            uint32_t al0 = *(const uint32_t*)q;
            uint32_t al1 = *(const uint32_t*)(q + 8 * ROWB);
            uint32_t al2 = *(const uint32_t*)(q + 16);
            uint32_t al3 = *(const uint32_t*)(q + 8 * ROWB + 16);
#pragma unroll
            for (int nt = 0; nt < 4; nt++)
                mma16816(acc[mt][nt], ah0, ah1, ah2, ah3, bh[nt][0], bh[nt][1]);
#pragma unroll
            for (int nt = 0; nt < 4; nt++)
                mma16816(acc[mt][nt], ah0, ah1, ah2, ah3, bl[nt][0], bl[nt][1]);
#pragma unroll
            for (int nt = 0; nt < 4; nt++)
                mma16816(acc[mt][nt], al0, al1, al2, al3, bh[nt][0], bh[nt][1]);
        }
    }
}

__device__ __forceinline__ void stage_copy(uint32_t sb32, int stage,
    const bf16* __restrict__ Ah, const bf16* __restrict__ Al,
    const bf16* __restrict__ Bh, const bf16* __restrict__ Bl,
    int bm, int bn, int N, int Kpad, int kk, int tid)
{
    uint32_t st = sb32 + stage * STG_SM;
#pragma unroll
    for (int c = 0; c < 8; c++) {
        int g    = c * 256 + tid;
        int tile = g >> 9;
        int rem  = g & 511;
        int row  = rem >> 2, col = rem & 3;
        uint32_t dst = st + tile * TILE_SM + row * ROWB + col * 16;
        const bf16* base;
        int rowg; uint32_t sz = 16;
        if (tile < 2) { base = tile ? Al : Ah; rowg = bm + row; }
        else {
            base = (tile == 3) ? Bl : Bh; rowg = bn + row;
            if (rowg >= N) { rowg = 0; sz = 0; }
        }
        cp_async16(dst, base + (size_t)rowg * Kpad + kk + col * 8, sz);
    }
}

template<int EM>
__global__ void __launch_bounds__(256, 2) mma_gemm2(
    const bf16* __restrict__ Ah, const bf16* __restrict__ Al,
    const bf16* __restrict__ Bh, const bf16* __restrict__ Bl,
    const float* __restrict__ bias, const float* __restrict__ e_aux,
    float* __restrict__ C, float* __restrict__ Cpart,
    int M, int N, int Kpad, int nchunks, int nsplit)
{
    extern __shared__ __align__(16) char smem[];
    uint32_t sb32 = smem_u32(smem);
    int tid  = threadIdx.x;
    int wid  = tid >> 5, lane = tid & 31;
    int wm   = wid >> 2, wn = wid & 3;
    int bm   = blockIdx.y * 128, bn = blockIdx.x * 128;
    int cpz  = (nchunks + nsplit - 1) / nsplit;
    int c0   = blockIdx.z * cpz;
    int c1   = min(nchunks, c0 + cpz);
    int nloc = c1 - c0;

    float acc[4][4][4];
#pragma unroll
    for (int a = 0; a < 4; a++)
#pragma unroll
        for (int b = 0; b < 4; b++)
#pragma unroll
            for (int c = 0; c < 4; c++) acc[a][b][c] = 0.0f;

    int npre = min(NSTAGE, nloc);
    for (int s = 0; s < npre; s++) {
        stage_copy(sb32, s, Ah, Al, Bh, Bl, bm, bn, N, Kpad, (c0 + s) * 32, tid);
        cp_commit();
    }

    for (int j = 0; j < nloc; j++) {
        cp_wait(min(nloc - 1 - j, NSTAGE - 1));
        __syncthreads();
        compute_chunk(smem + (j % NSTAGE) * STG_SM, wm, wn, lane, acc);
        __syncthreads();
        if (j + NSTAGE < nloc) {
            stage_copy(sb32, j % NSTAGE, Ah, Al, Bh, Bl, bm, bn, N, Kpad,
                       (c0 + j + NSTAGE) * 32, tid);
            cp_commit();
        }
    }

    int l4 = lane >> 2, lt = lane & 3;
#pragma unroll
    for (int mt = 0; mt < 4; mt++) {
#pragma unroll
        for (int nt = 0; nt < 4; nt++) {
            int r0 = bm + wm * 64 + mt * 16 + l4;
            int cc = bn + wn * 32 + nt * 8 + lt * 2;
            float* a4 = acc[mt][nt];
            if (nsplit == 1) {
                if (cc < N) {
                    C[(size_t)r0 * N + cc]       = apply_epi<EM>(a4[0], r0, cc, bias, nullptr, e_aux, N);
                    C[(size_t)(r0 + 8) * N + cc] = apply_epi<EM>(a4[2], r0 + 8, cc, bias, nullptr, e_aux, N);
                }
                if (cc + 1 < N) {
                    C[(size_t)r0 * N + cc + 1]       = apply_epi<EM>(a4[1], r0, cc + 1, bias, nullptr, e_aux, N);
                    C[(size_t)(r0 + 8) * N + cc + 1] = apply_epi<EM>(a4[3], r0 + 8, cc + 1, bias, nullptr, e_aux, N);
                }
            } else {
                float* P = Cpart + (size_t)blockIdx.z * M * N;
                if (cc < N) {
                    P[(size_t)r0 * N + cc]       = a4[0];
                    P[(size_t)(r0 + 8) * N + cc] = a4[2];
                }
                if (cc + 1 < N) {
                    P[(size_t)r0 * N + cc + 1]       = a4[1];
                    P[(size_t)(r0 + 8) * N + cc + 1] = a4[3];
                }
            }
        }
    }
}

// ---------------- split-K reduction + epilogue (float4) ----------------
template<int EM>
__global__ void reduce_epi(const float* __restrict__ Cpart,
    const float* __restrict__ bias, const float* __restrict__ resid,
    const float* __restrict__ e_aux, float* __restrict__ C,
    bf16* __restrict__ Chi, bf16* __restrict__ Clo, int M, int N, int S)
{
    int idx4 = (blockIdx.x * 256 + threadIdx.x) * 4;
    if (idx4 >= M * N) return;
    float4 s = make_float4(0.f, 0.f, 0.f, 0.f);
    for (int z = 0; z < S; z++) {
        float4 p = *(const float4*)(Cpart + (size_t)z * M * N + idx4);
        s.x += p.x; s.y += p.y; s.z += p.z; s.w += p.w;
    }
    int gm = idx4 / N, gn = idx4 - gm * N;      // N % 4 == 0 -> no row split
    float v0 = apply_epi<EM>(s.x, gm, gn,     bias, resid, e_aux, N);
    float v1 = apply_epi<EM>(s.y, gm, gn + 1, bias, resid, e_aux, N);
    float v2 = apply_epi<EM>(s.z, gm, gn + 2, bias, resid, e_aux, N);
    float v3 = apply_epi<EM>(s.w, gm, gn + 3, bias, resid, e_aux, N);
    if (C) *(float4*)(C + idx4) = make_float4(v0, v1, v2, v3);
    if (Chi) {
        *(uint2*)(Chi + idx4) = make_uint2(pk2(v0, v1), pk2(v2, v3));
        float h0 = __bfloat162float(__float2bfloat16(v0));
        float h1 = __bfloat162float(__float2bfloat16(v1));
        float h2 = __bfloat162float(__float2bfloat16(v2));
        float h3 = __bfloat162float(__float2bfloat16(v3));
        *(uint2*)(Clo + idx4) = make_uint2(pk2(v0 - h0, v1 - h1), pk2(v2 - h2, v3 - h3));
    }
}

// ---------------- style ----------------
__global__ void style_k(const float* __restrict__ oh, const float* __restrict__ W,
                        float* __restrict__ st)
{
    int d = blockIdx.x * blockDim.x + threadIdx.x;
    if (d < DMODEL) {
        float s = 0.0f;
#pragma unroll
        for (int n = 0; n < 8; n++) s += oh[n] * W[d * 8 + n];
        st[d] = s;
    }
}

// ---------------- LayerNorm ----------------
__device__ __forceinline__ float block_sum(float v, float* sred)
{
    __syncthreads();
#pragma unroll
    for (int o = 16; o; o >>= 1) v += __shfl_xor_sync(0xffffffffu, v, o);
    int w = threadIdx.x >> 5, l = threadIdx.x & 31;
    if (l == 0) sred[w] = v;
    __syncthreads();
    float t = (l < 8) ? sred[l] : 0.0f;
#pragma unroll
    for (int o = 4; o; o >>= 1) t += __shfl_xor_sync(0xffffffffu, t, o);
    if (threadIdx.x == 0) sred[0] = t;
    __syncthreads();
    return sred[0];
}

__global__ void __launch_bounds__(256) layernorm_k(float* __restrict__ x,
    const float* __restrict__ g, const float* __restrict__ b,
    bf16* __restrict__ hi, bf16* __restrict__ lo)
{
    __shared__ float sred[32];
    int row = blockIdx.x, tid = threadIdx.x;
    float v[4];
    float s = 0.0f;
#pragma unroll
    for (int i = 0; i < 4; i++) { v[i] = x[row * DMODEL + i * 256 + tid]; s += v[i]; }
    float mean = block_sum(s, sred) * (1.0f / 1024.0f);
    float sq = 0.0f;
#pragma unroll
    for (int i = 0; i < 4; i++) { float d = v[i] - mean; sq += d * d; }
    float var  = block_sum(sq, sred) * (1.0f / 1024.0f);
    float rstd = rsqrtf(var + 1e-5f);
#pragma unroll
    for (int i = 0; i < 4; i++) {
        int c = i * 256 + tid;
        float o = (v[i] - mean) * rstd * g[c] + b[c];
        x[row * DMODEL + c] = o;
        if (hi) split_write(hi, lo, (size_t)row * DMODEL + c, o);
    }
}

// ---------------- fused self-attention ----------------
#define ATT_BQ 16
#define ATT_KT 64
#define SPAD   516
#define QS_FLOATS (256 * 17)
#define SS_FLOATS (ATT_BQ * SPAD)
#define KV_FLOATS (256 * 68)
#define ATT_SMEM_BYTES ((QS_FLOATS + SS_FLOATS + KV_FLOATS) * 4)

__global__ void __launch_bounds__(256) attention_sa(const float* __restrict__ qkv,
                                                    bf16* __restrict__ ohi,
                                                    bf16* __restrict__ olo)
{
    extern __shared__ __align__(16) float sm[];
    float* Qs = sm;
    float* Ss = sm + QS_FLOATS;
    float* KV = sm + QS_FLOATS + SS_FLOATS;

    int h   = blockIdx.y;
    int q0  = blockIdx.x * ATT_BQ;
    int tid = threadIdx.x;
    float slope = exp2f(-2.0f * (float)(h + 1));

    for (int idx = tid; idx < ATT_BQ * 256; idx += 256) {
        int qi = idx >> 8, d = idx & 255;
        Qs[d * 17 + qi] = qkv[(size_t)(q0 + qi) * 3072 + h * 256 + d];
    }
    __syncthreads();

    int qmax = q0 + ATT_BQ - 1;
    int qi   = tid >> 4;

    {
        int kk0 = (tid & 15) * 4;
        for (int s0 = 0; s0 < TLEN; s0 += ATT_KT) {
            if (s0 > qmax) {
                for (int idx = tid; idx < ATT_BQ * ATT_KT; idx += 256) {
                    int rr = idx >> 6, cc = idx & 63;
                    Ss[rr * SPAD + s0 + cc] = -1e30f;
                }
                continue;
            }
            for (int idx = tid; idx < ATT_KT * 256; idx += 256) {
                int kk = idx >> 8, d = idx & 255;
                KV[d * 68 + kk] = qkv[(size_t)(s0 + kk) * 3072 + 1024 + h * 256 + d];
            }
            __syncthreads();
            float a0 = 0.f, a1 = 0.f, a2 = 0.f, a3 = 0.f;
#pragma unroll 4
            for (int d = 0; d < 256; d++) {
                float  qv = Qs[d * 17 + qi];
                float4 kv = *(const float4*)&KV[d * 68 + kk0];
                a0 = fmaf(qv, kv.x, a0);
                a1 = fmaf(qv, kv.y, a1);
                a2 = fmaf(qv, kv.z, a2);
                a3 = fmaf(qv, kv.w, a3);
            }
            int i  = q0 + qi;
            int jb = s0 + kk0;
            float accs[4] = {a0, a1, a2, a3};
#pragma unroll
            for (int c = 0; c < 4; c++) {
                int jj = jb + c;
                float mv = (jj > i) ? -1e30f : (-slope * (float)((i - jj) / 25));
                Ss[qi * SPAD + jj] = accs[c] * 0.0625f + mv;
            }
            __syncthreads();
        }
    }
    __syncthreads();

    {
        int warp = tid >> 5, lane = tid & 31;
        for (int rr = warp; rr < ATT_BQ; rr += 8) {
            float mx = -1e30f;
            for (int jj = lane; jj < TLEN; jj += 32) mx = fmaxf(mx, Ss[rr * SPAD + jj]);
#pragma unroll
            for (int o = 16; o; o >>= 1) mx = fmaxf(mx, __shfl_xor_sync(0xffffffffu, mx, o));
            float sum = 0.0f;
            for (int jj = lane; jj < TLEN; jj += 32) {
                float e = expf(Ss[rr * SPAD + jj] - mx);
                Ss[rr * SPAD + jj] = e;
                sum += e;
            }
#pragma unroll
            for (int o = 16; o; o >>= 1) sum += __shfl_xor_sync(0xffffffffu, sum, o);
            float inv = 1.0f / sum;
            for (int jj = lane; jj < TLEN; jj += 32) Ss[rr * SPAD + jj] *= inv;
        }
    }
    __syncthreads();

    float acc[16];
#pragma unroll
    for (int i = 0; i < 16; i++) acc[i] = 0.0f;
    int d0 = (tid & 15) * 16;

    for (int s0 = 0; s0 <= qmax; s0 += ATT_KT) {
        for (int idx = tid; idx < ATT_KT * 256; idx += 256) {
            int kk = idx >> 8, d = idx & 255;
            KV[kk * 256 + d] = qkv[(size_t)(s0 + kk) * 3072 + 2048 + h * 256 + d];
        }
        __syncthreads();
        for (int kk = 0; kk < ATT_KT; kk++) {
            float a = Ss[qi * SPAD + s0 + kk];
            const float4* vp = (const float4*)&KV[kk * 256 + d0];
            float4 v0 = vp[0], v1 = vp[1], v2 = vp[2], v3 = vp[3];
            acc[0]  = fmaf(a, v0.x, acc[0]);  acc[1]  = fmaf(a, v0.y, acc[1]);
            acc[2]  = fmaf(a, v0.z, acc[2]);  acc[3]  = fmaf(a, v0.w, acc[3]);
            acc[4]  = fmaf(a, v1.x, acc[4]);  acc[5]  = fmaf(a, v1.y, acc[5]);
            acc[6]  = fmaf(a, v1.z, acc[6]);  acc[7]  = fmaf(a, v1.w, acc[7]);
            acc[8]  = fmaf(a, v2.x, acc[8]);  acc[9]  = fmaf(a, v2.y, acc[9]);
            acc[10] = fmaf(a, v2.z, acc[10]); acc[11] = fmaf(a, v2.w, acc[11]);
            acc[12] = fmaf(a, v3.x, acc[12]); acc[13] = fmaf(a, v3.y, acc[13]);
            acc[14] = fmaf(a, v3.z, acc[14]); acc[15] = fmaf(a, v3.w, acc[15]);
        }
        __syncthreads();
    }
#pragma unroll
    for (int c = 0; c < 16; c++)
        split_write(ohi, olo, (size_t)(q0 + qi) * 1024 + h * 256 + d0 + c, acc[c]);
}

// ---------------- launcher ----------------
extern "C" void kernel_launch(void* const* d_in, const int* in_sizes, int n_in,
                              void* d_out, int out_size)
{
    const float* audio   = (const float*)d_in[0];
    const float* vertice = (const float*)d_in[1];
    const float* tmpl    = (const float*)d_in[2];
    const float* one_hot = (const float*)d_in[3];
    const float* W_af    = (const float*)d_in[4];
    const float* b_af    = (const float*)d_in[5];
    const float* W_vm    = (const float*)d_in[6];
    const float* b_vm    = (const float*)d_in[7];
    const float* W_obj   = (const float*)d_in[8];
    const float* Wqkv_sa = (const float*)d_in[9];
    const float* bqkv_sa = (const float*)d_in[10];
    const float* Wo_sa   = (const float*)d_in[11];
    const float* bo_sa   = (const float*)d_in[12];
    const float* Wqkv_ca = (const float*)d_in[13];
    const float* bqkv_ca = (const float*)d_in[14];
    const float* Wo_ca   = (const float*)d_in[15];
    const float* bo_ca   = (const float*)d_in[16];
    const float* W1      = (const float*)d_in[17];
    const float* b1      = (const float*)d_in[18];
    const float* W2      = (const float*)d_in[19];
    const float* b2      = (const float*)d_in[20];
    const float* g1      = (const float*)d_in[21];
    const float* be1     = (const float*)d_in[22];
    const float* g2      = (const float*)d_in[23];
    const float* be2     = (const float*)d_in[24];
    const float* g3      = (const float*)d_in[25];
    const float* be3     = (const float*)d_in[26];
    const float* W_vr    = (const float*)d_in[27];
    const float* b_vr    = (const float*)d_in[28];
    float* out = (float*)d_out;

    float *style, *x, *y, *qkv, *part;
    cudaGetSymbolAddress((void**)&style, g_style);
    cudaGetSymbolAddress((void**)&x,     g_x);
    cudaGetSymbolAddress((void**)&y,     g_y);
    cudaGetSymbolAddress((void**)&qkv,   g_qkv);
    cudaGetSymbolAddress((void**)&part,  g_part);

#define SYM(p, s) bf16* p; cudaGetSymbolAddress((void**)&p, s)
    SYM(Waf_h, g_Waf_h);  SYM(Waf_l, g_Waf_l);
    SYM(Wvm_h, g_Wvm_h);  SYM(Wvm_l, g_Wvm_l);
    SYM(Wqkv_h, g_Wqkv_h); SYM(Wqkv_l, g_Wqkv_l);
    SYM(Wosa_h, g_Wosa_h); SYM(Wosa_l, g_Wosa_l);
    SYM(Wvca_h, g_Wvca_h); SYM(Wvca_l, g_Wvca_l);
    SYM(Woca_h, g_Woca_h); SYM(Woca_l, g_Woca_l);
    SYM(W1_h, g_W1_h);    SYM(W1_l, g_W1_l);
    SYM(W2_h, g_W2_h);    SYM(W2_l, g_W2_l);
    SYM(Wvr_h, g_Wvr_h);  SYM(Wvr_l, g_Wvr_l);
    SYM(aud_h, g_aud_h);  SYM(aud_l, g_aud_l);
    SYM(vin_h, g_vin_h);  SYM(vin_l, g_vin_l);
    SYM(hid_h, g_hid_h);  SYM(hid_l, g_hid_l);
    SYM(xa_h, g_xa_h);    SYM(xa_l, g_xa_l);
    SYM(x2_h, g_x2_h);    SYM(x2_l, g_x2_l);
    SYM(y2_h, g_y2_h);    SYM(y2_l, g_y2_l);
    SYM(attn_h, g_attn_h); SYM(attn_l, g_attn_l);
    SYM(vca_h, g_vca_h);  SYM(vca_l, g_vca_l);
    SYM(ff_h, g_ff_h);    SYM(ff_l, g_ff_l);
#undef SYM

    cudaFuncSetAttribute(attention_sa,
        cudaFuncAttributeMaxDynamicSharedMemorySize, ATT_SMEM_BYTES);
    cudaFuncSetAttribute(mma_gemm2<0>,
        cudaFuncAttributeMaxDynamicSharedMemorySize, GEMM_SMEM_BYTES);
    cudaFuncSetAttribute(mma_gemm2<4>,
        cudaFuncAttributeMaxDynamicSharedMemorySize, GEMM_SMEM_BYTES);

    const int M = TLEN;

    // ---- single merged conversion launch (16 elems/thread) ----
    {
        ConvJobs J;
        J.tmpl = tmpl;
        const float* srcs[NJOBS] = { W_af, audio, W_vm, vertice, Wqkv_sa,
                                     Wo_sa, Wqkv_ca + (size_t)2048*DMODEL, Wo_ca,
                                     W1, W2, W_vr };
        bf16* his[NJOBS] = { Waf_h, aud_h, Wvm_h, vin_h, Wqkv_h, Wosa_h, Wvca_h,
                             Woca_h, W1_h, W2_h, Wvr_h };
        bf16* los[NJOBS] = { Waf_l, aud_l, Wvm_l, vin_l, Wqkv_l, Wosa_l, Wvca_l,
                             Woca_l, W1_l, W2_l, Wvr_l };
        int Ks[NJOBS]    = { AUDDIM, AUDDIM, V3DIM, V3DIM, DMODEL, DMODEL, DMODEL,
                             DMODEL, DMODEL, DFFDIM, DMODEL };
        int Kps[NJOBS]   = { AUDDIM, AUDDIM, KVPAD, KVPAD, DMODEL, DMODEL, DMODEL,
                             DMODEL, DMODEL, DFFDIM, DMODEL };
        int rows[NJOBS]  = { DMODEL, TLEN, DMODEL, TLEN, 3*DMODEL, DMODEL, DMODEL,
                             DMODEL, DFFDIM, DMODEL, V3DIM };
        int modes[NJOBS] = { 0, 0, 0, 1, 0, 0, 0, 0, 0, 0, 0 };
        int nb = 0;
        for (int t = 0; t < NJOBS; t++) {
            J.src[t] = srcs[t]; J.hi[t] = his[t]; J.lo[t] = los[t];
            J.K[t] = Ks[t]; J.Kpad[t] = Kps[t]; J.mode[t] = modes[t];
            J.total[t] = (long)rows[t] * Kps[t];
            nb += (int)((J.total[t] + 4095) / 4096);
            J.blk_end[t] = nb;
        }
        conv_all<<<nb, 256>>>(J);
    }
    style_k<<<4, 256>>>(one_hot, W_obj, style);

    // ---- hidden = audio @ W_af^T + b_af  (K=768: 24 chunks, split 4) ----
    mma_gemm2<0><<<dim3(8,4,4), 256, GEMM_SMEM_BYTES>>>(
        aud_h, aud_l, Waf_h, Waf_l, nullptr, nullptr,
        nullptr, part, M, DMODEL, AUDDIM, 24, 4);
    reduce_epi<0><<<(M*DMODEL/4+255)/256, 256>>>(part, b_af, nullptr, nullptr,
        nullptr, hid_h, hid_l, M, DMODEL, 4);

    // ---- x = vin @ W_vm^T + b_vm + style + PE  (472 chunks, split 9) ----
    mma_gemm2<0><<<dim3(8,4,9), 256, GEMM_SMEM_BYTES>>>(
        vin_h, vin_l, Wvm_h, Wvm_l, nullptr, nullptr,
        nullptr, part, M, DMODEL, KVPAD, 472, 9);
    reduce_epi<3><<<(M*DMODEL/4+255)/256, 256>>>(part, b_vm, nullptr, style,
        x, xa_h, xa_l, M, DMODEL, 9);

    // ---- qkv = xa @ Wqkv^T + bqkv  (N=3072, split 2) ----
    mma_gemm2<0><<<dim3(24,4,2), 256, GEMM_SMEM_BYTES>>>(
        xa_h, xa_l, Wqkv_h, Wqkv_l, nullptr, nullptr,
        nullptr, part, M, 3*DMODEL, DMODEL, 32, 2);
    reduce_epi<0><<<(M*3*DMODEL/4+255)/256, 256>>>(part, bqkv_sa, nullptr, nullptr,
        qkv, nullptr, nullptr, M, 3*DMODEL, 2);

    attention_sa<<<dim3(TLEN/ATT_BQ, NHEAD), 256, ATT_SMEM_BYTES>>>(qkv, attn_h, attn_l);

    // ---- y = x + attn @ Wo_sa^T + bo_sa ; LN1 ----
    mma_gemm2<0><<<dim3(8,4,4), 256, GEMM_SMEM_BYTES>>>(
        attn_h, attn_l, Wosa_h, Wosa_l, nullptr, nullptr,
        nullptr, part, M, DMODEL, DMODEL, 32, 4);
    reduce_epi<2><<<(M*DMODEL/4+255)/256, 256>>>(part, bo_sa, x, nullptr,
        y, nullptr, nullptr, M, DMODEL, 4);
    layernorm_k<<<M, 256>>>(y, g1, be1, nullptr, nullptr);

    // ---- cross-attn (diagonal) ----
    mma_gemm2<0><<<dim3(8,4,4), 256, GEMM_SMEM_BYTES>>>(
        hid_h, hid_l, Wvca_h, Wvca_l, nullptr, nullptr,
        nullptr, part, M, DMODEL, DMODEL, 32, 4);
    reduce_epi<0><<<(M*DMODEL/4+255)/256, 256>>>(part, bqkv_ca + 2048, nullptr, nullptr,
        nullptr, vca_h, vca_l, M, DMODEL, 4);
    mma_gemm2<0><<<dim3(8,4,4), 256, GEMM_SMEM_BYTES>>>(
        vca_h, vca_l, Woca_h, Woca_l, nullptr, nullptr,
        nullptr, part, M, DMODEL, DMODEL, 32, 4);
    reduce_epi<2><<<(M*DMODEL/4+255)/256, 256>>>(part, bo_ca, y, nullptr,
        x, nullptr, nullptr, M, DMODEL, 4);
    layernorm_k<<<M, 256>>>(x, g2, be2, x2_h, x2_l);

    // ---- FFN ----
    mma_gemm2<0><<<dim3(16,4,2), 256, GEMM_SMEM_BYTES>>>(
        x2_h, x2_l, W1_h, W1_l, nullptr, nullptr,
        nullptr, part, M, DFFDIM, DMODEL, 32, 2);
    reduce_epi<1><<<(M*DFFDIM/4+255)/256, 256>>>(part, b1, nullptr, nullptr,
        nullptr, ff_h, ff_l, M, DFFDIM, 2);
    mma_gemm2<0><<<dim3(8,4,4), 256, GEMM_SMEM_BYTES>>>(
        ff_h, ff_l, W2_h, W2_l, nullptr, nullptr,
        nullptr, part, M, DMODEL, DFFDIM, 64, 4);
    reduce_epi<2><<<(M*DMODEL/4+255)/256, 256>>>(part, b2, x, nullptr,
        y, nullptr, nullptr, M, DMODEL, 4);
    layernorm_k<<<M, 256>>>(y, g3, be3, y2_h, y2_l);

    // ---- out = y @ W_vr^T + b_vr + template ----
    mma_gemm2<4><<<dim3((V3DIM+127)/128, 4, 1), 256, GEMM_SMEM_BYTES>>>(
        y2_h, y2_l, Wvr_h, Wvr_l, b_vr, tmpl,
        out, nullptr, M, V3DIM, DMODEL, 32, 1);
}

// round 15
// speedup vs baseline: 1.9559x; 1.0052x over previous
#include <cuda_runtime.h>
#include <cuda_bf16.h>
#include <math.h>
#include <stdint.h>

typedef __nv_bfloat16 bf16;

// ---------------- problem constants ----------------
#define DMODEL 1024
#define NHEAD  4
#define HDIM   256
#define TLEN   512
#define V3DIM  15069
#define KVPAD  15104
#define DFFDIM 2048
#define AUDDIM 768

// ---------------- fp32 scratch ----------------
__device__ float g_style [DMODEL];
__device__ float g_x     [TLEN * DMODEL];
__device__ float g_y     [TLEN * DMODEL];
__device__ float g_qkv   [TLEN * 3 * DMODEL];
__device__ float g_part  [12 * TLEN * DMODEL];

// ---------------- bf16 hi/lo buffers ----------------
__device__ bf16 g_Waf_h [DMODEL * AUDDIM],  g_Waf_l [DMODEL * AUDDIM];
__device__ bf16 g_Wvm_h [DMODEL * KVPAD],   g_Wvm_l [DMODEL * KVPAD];
__device__ bf16 g_Wqkv_h[3 * DMODEL * DMODEL], g_Wqkv_l[3 * DMODEL * DMODEL];
__device__ bf16 g_Wosa_h[DMODEL * DMODEL],  g_Wosa_l[DMODEL * DMODEL];
__device__ bf16 g_Wvca_h[DMODEL * DMODEL],  g_Wvca_l[DMODEL * DMODEL];
__device__ bf16 g_Woca_h[DMODEL * DMODEL],  g_Woca_l[DMODEL * DMODEL];
__device__ bf16 g_W1_h  [DFFDIM * DMODEL],  g_W1_l  [DFFDIM * DMODEL];
__device__ bf16 g_W2_h  [DMODEL * DFFDIM],  g_W2_l  [DMODEL * DFFDIM];
__device__ bf16 g_Wvr_h [V3DIM * DMODEL],   g_Wvr_l [V3DIM * DMODEL];

__device__ bf16 g_aud_h [TLEN * AUDDIM],  g_aud_l [TLEN * AUDDIM];
__device__ bf16 g_vin_h [TLEN * KVPAD],   g_vin_l [TLEN * KVPAD];
__device__ bf16 g_hid_h [TLEN * DMODEL],  g_hid_l [TLEN * DMODEL];
__device__ bf16 g_xa_h  [TLEN * DMODEL],  g_xa_l  [TLEN * DMODEL];
__device__ bf16 g_x2_h  [TLEN * DMODEL],  g_x2_l  [TLEN * DMODEL];
__device__ bf16 g_y2_h  [TLEN * DMODEL],  g_y2_l  [TLEN * DMODEL];
__device__ bf16 g_attn_h[TLEN * DMODEL],  g_attn_l[TLEN * DMODEL];
__device__ bf16 g_vca_h [TLEN * DMODEL],  g_vca_l [TLEN * DMODEL];
__device__ bf16 g_ff_h  [TLEN * DFFDIM],  g_ff_l  [TLEN * DFFDIM];

// ---------------- helpers ----------------
__device__ __forceinline__ uint32_t smem_u32(const void* p){
    uint32_t a;
    asm("{ .reg .u64 t; cvta.to.shared.u64 t, %1; cvt.u32.u64 %0, t; }" : "=r"(a) : "l"(p));
    return a;
}
__device__ __forceinline__ void cp_async16(uint32_t dst, const void* src, uint32_t sz){
    asm volatile("cp.async.cg.shared.global [%0], [%1], 16, %2;" :: "r"(dst), "l"(src), "r"(sz));
}
__device__ __forceinline__ void cp_commit(){
    asm volatile("cp.async.commit_group;" ::: "memory");
}
__device__ __forceinline__ void cp_wait(int allow){
    if (allow <= 0)      asm volatile("cp.async.wait_group 0;" ::: "memory");
    else                 asm volatile("cp.async.wait_group 1;" ::: "memory");
}
__device__ __forceinline__ void split_write(bf16* hi, bf16* lo, size_t o, float v){
    bf16 h = __float2bfloat16(v);
    hi[o] = h;
    lo[o] = __float2bfloat16(v - __bfloat162float(h));
}
__device__ __forceinline__ uint32_t pk2(float a, float b){
    __nv_bfloat162 t(__float2bfloat16(a), __float2bfloat16(b));
    uint32_t u; memcpy(&u, &t, 4); return u;
}

// ---------------- epilogue ----------------
// EM: 0=+bias ; 1=+bias,relu ; 2=+bias,+resid ; 3=+bias,+style,+PE ; 4=+bias,+template[n]
template<int EM>
__device__ __forceinline__ float apply_epi(float v, int gm, int gn,
    const float* bias, const float* resid, const float* e_aux, int N)
{
    v += bias[gn];
    if (EM == 1) v = fmaxf(v, 0.0f);
    if (EM == 2) v += resid[(size_t)gm * N + gn];
    if (EM == 3) {
        v += e_aux[gn];
        int   p   = gm % 25;
        int   e   = gn & ~1;
        float dv  = expf((float)e * (-9.210340371976184f / 1024.0f));
        float ang = (float)p * dv;
        v += (gn & 1) ? cosf(ang) : sinf(ang);
    }
    if (EM == 4) v += e_aux[gn];
    return v;
}

// ---------------- merged conversion kernel: 16 elems/thread ----------------
#define NJOBS 11
struct ConvJobs {
    const float* src[NJOBS];
    bf16* hi[NJOBS];
    bf16* lo[NJOBS];
    int   K[NJOBS];
    int   Kpad[NJOBS];
    long  total[NJOBS];
    int   mode[NJOBS];
    int   blk_end[NJOBS];
    const float* tmpl;
};

__global__ void __launch_bounds__(256) conv_all(ConvJobs J)
{
    int b = blockIdx.x;
    int j = 0;
#pragma unroll
    for (int t = 0; t < NJOBS; t++) if (b >= J.blk_end[t]) j = t + 1;
    int b0    = (j == 0) ? 0 : J.blk_end[j - 1];
    long e0   = (long)(b - b0) * 4096 + threadIdx.x * 4;
    int Kpad  = J.Kpad[j], K = J.K[j];
    long tot  = J.total[j];
    const float* src = J.src[j];
    int mode  = J.mode[j];
    bf16* hi  = J.hi[j];
    bf16* lo  = J.lo[j];

#pragma unroll
    for (int q = 0; q < 4; q++) {
        long e = e0 + q * 1024;
        if (e >= tot) break;
        int row = (int)(e / Kpad);
        int kp  = (int)(e - (long)row * Kpad);
        float v[4];
        if (mode == 1) {
            if (row == 0) { v[0] = v[1] = v[2] = v[3] = 0.0f; }
            else {
                const float* s = src + (size_t)(row - 1) * K;
#pragma unroll
                for (int i = 0; i < 4; i++) {
                    int k = kp + i;
                    v[i] = (k < K) ? s[k] - J.tmpl[k] : 0.0f;
                }
            }
        } else {
            const float* s = src + (size_t)row * K;
#pragma unroll
            for (int i = 0; i < 4; i++) {
                int k = kp + i;
                v[i] = (k < K) ? s[k] : 0.0f;
            }
        }
        float h0 = __bfloat162float(__float2bfloat16(v[0]));
        float h1 = __bfloat162float(__float2bfloat16(v[1]));
        float h2 = __bfloat162float(__float2bfloat16(v[2]));
        float h3 = __bfloat162float(__float2bfloat16(v[3]));
        size_t o = (size_t)row * Kpad + kp;
        *(uint2*)(hi + o) = make_uint2(pk2(h0, h1), pk2(h2, h3));
        *(uint2*)(lo + o) = make_uint2(pk2(v[0] - h0, v[1] - h1),
                                       pk2(v[2] - h2, v[3] - h3));
    }
}

// ---------------- mma.sync GEMM (champion) ----------------
__device__ __forceinline__ void mma16816(float* c,
    uint32_t a0, uint32_t a1, uint32_t a2, uint32_t a3,
    uint32_t b0, uint32_t b1)
{
    asm volatile("mma.sync.aligned.m16n8k16.row.col.f32.bf16.bf16.f32 "
        "{%0,%1,%2,%3}, {%4,%5,%6,%7}, {%8,%9}, {%0,%1,%2,%3};"
        : "+f"(c[0]), "+f"(c[1]), "+f"(c[2]), "+f"(c[3])
        : "r"(a0), "r"(a1), "r"(a2), "r"(a3), "r"(b0), "r"(b1));
}

#define ROWB    80
#define TILE_SM (128 * ROWB)
#define STG_SM  (4 * TILE_SM)
#define NSTAGE  2
#define GEMM_SMEM_BYTES (NSTAGE * STG_SM)

__device__ __forceinline__ void compute_chunk(const char* base, int wm, int wn,
                                              int lane, float (&acc)[4][4][4])
{
    const char* sAh = base;
    const char* sAl = base + TILE_SM;
    const char* sBh = base + 2 * TILE_SM;
    const char* sBl = base + 3 * TILE_SM;
    int l4 = lane >> 2, lt = (lane & 3) * 4;

#pragma unroll
    for (int ks = 0; ks < 2; ks++) {
        int kb = ks * 32 + lt;
        uint32_t bh[4][2], bl[4][2];
#pragma unroll
        for (int nt = 0; nt < 4; nt++) {
            int nr = wn * 32 + nt * 8 + l4;
            const char* p = sBh + nr * ROWB + kb;
            bh[nt][0] = *(const uint32_t*)p;
            bh[nt][1] = *(const uint32_t*)(p + 16);
            const char* q = sBl + nr * ROWB + kb;
            bl[nt][0] = *(const uint32_t*)q;
            bl[nt][1] = *(const uint32_t*)(q + 16);
        }
#pragma unroll
        for (int mt = 0; mt < 4; mt++) {
            int r0 = wm * 64 + mt * 16 + l4;
            const char* p = sAh + r0 * ROWB + kb;
            uint32_t ah0 = *(const uint32_t*)p;
            uint32_t ah1 = *(const uint32_t*)(p + 8 * ROWB);
            uint32_t ah2 = *(const uint32_t*)(p + 16);
            uint32_t ah3 = *(const uint32_t*)(p + 8 * ROWB + 16);
            const char* q = sAl + r0 * ROWB + kb;
            uint32_t al0 = *(const uint32_t*)q;
            uint32_t al1 = *(const uint32_t*)(q + 8 * ROWB);
            uint32_t al2 = *(const uint32_t*)(q + 16);
            uint32_t al3 = *(const uint32_t*)(q + 8 * ROWB + 16);
#pragma unroll
            for (int nt = 0; nt < 4; nt++)
                mma16816(acc[mt][nt], ah0, ah1, ah2, ah3, bh[nt][0], bh[nt][1]);
#pragma unroll
            for (int nt = 0; nt < 4; nt++)
                mma16816(acc[mt][nt], ah0, ah1, ah2, ah3, bl[nt][0], bl[nt][1]);
#pragma unroll
            for (int nt = 0; nt < 4; nt++)
                mma16816(acc[mt][nt], al0, al1, al2, al3, bh[nt][0], bh[nt][1]);
        }
    }
}

__device__ __forceinline__ void stage_copy(uint32_t sb32, int stage,
    const bf16* __restrict__ Ah, const bf16* __restrict__ Al,
    const bf16* __restrict__ Bh, const bf16* __restrict__ Bl,
    int bm, int bn, int N, int Kpad, int kk, int tid)
{
    uint32_t st = sb32 + stage * STG_SM;
#pragma unroll
    for (int c = 0; c < 8; c++) {
        int g    = c * 256 + tid;
        int tile = g >> 9;
        int rem  = g & 511;
        int row  = rem >> 2, col = rem & 3;
        uint32_t dst = st + tile * TILE_SM + row * ROWB + col * 16;
        const bf16* base;
        int rowg; uint32_t sz = 16;
        if (tile < 2) { base = tile ? Al : Ah; rowg = bm + row; }
        else {
            base = (tile == 3) ? Bl : Bh; rowg = bn + row;
            if (rowg >= N) { rowg = 0; sz = 0; }
        }
        cp_async16(dst, base + (size_t)rowg * Kpad + kk + col * 8, sz);
    }
}

template<int EM>
__global__ void __launch_bounds__(256, 2) mma_gemm2(
    const bf16* __restrict__ Ah, const bf16* __restrict__ Al,
    const bf16* __restrict__ Bh, const bf16* __restrict__ Bl,
    const float* __restrict__ bias, const float* __restrict__ e_aux,
    float* __restrict__ C, float* __restrict__ Cpart,
    int M, int N, int Kpad, int nchunks, int nsplit)
{
    extern __shared__ __align__(16) char smem[];
    uint32_t sb32 = smem_u32(smem);
    int tid  = threadIdx.x;
    int wid  = tid >> 5, lane = tid & 31;
    int wm   = wid >> 2, wn = wid & 3;
    int bm   = blockIdx.y * 128, bn = blockIdx.x * 128;
    int cpz  = (nchunks + nsplit - 1) / nsplit;
    int c0   = blockIdx.z * cpz;
    int c1   = min(nchunks, c0 + cpz);
    int nloc = c1 - c0;

    float acc[4][4][4];
#pragma unroll
    for (int a = 0; a < 4; a++)
#pragma unroll
        for (int b = 0; b < 4; b++)
#pragma unroll
            for (int c = 0; c < 4; c++) acc[a][b][c] = 0.0f;

    int npre = min(NSTAGE, nloc);
    for (int s = 0; s < npre; s++) {
        stage_copy(sb32, s, Ah, Al, Bh, Bl, bm, bn, N, Kpad, (c0 + s) * 32, tid);
        cp_commit();
    }

    for (int j = 0; j < nloc; j++) {
        cp_wait(min(nloc - 1 - j, NSTAGE - 1));
        __syncthreads();
        compute_chunk(smem + (j % NSTAGE) * STG_SM, wm, wn, lane, acc);
        __syncthreads();
        if (j + NSTAGE < nloc) {
            stage_copy(sb32, j % NSTAGE, Ah, Al, Bh, Bl, bm, bn, N, Kpad,
                       (c0 + j + NSTAGE) * 32, tid);
            cp_commit();
        }
    }

    int l4 = lane >> 2, lt = lane & 3;
#pragma unroll
    for (int mt = 0; mt < 4; mt++) {
#pragma unroll
        for (int nt = 0; nt < 4; nt++) {
            int r0 = bm + wm * 64 + mt * 16 + l4;
            int cc = bn + wn * 32 + nt * 8 + lt * 2;
            float* a4 = acc[mt][nt];
            if (nsplit == 1) {
                if (cc < N) {
                    C[(size_t)r0 * N + cc]       = apply_epi<EM>(a4[0], r0, cc, bias, nullptr, e_aux, N);
                    C[(size_t)(r0 + 8) * N + cc] = apply_epi<EM>(a4[2], r0 + 8, cc, bias, nullptr, e_aux, N);
                }
                if (cc + 1 < N) {
                    C[(size_t)r0 * N + cc + 1]       = apply_epi<EM>(a4[1], r0, cc + 1, bias, nullptr, e_aux, N);
                    C[(size_t)(r0 + 8) * N + cc + 1] = apply_epi<EM>(a4[3], r0 + 8, cc + 1, bias, nullptr, e_aux, N);
                }
            } else {
                float* P = Cpart + (size_t)blockIdx.z * M * N;
                if (cc < N) {
                    P[(size_t)r0 * N + cc]       = a4[0];
                    P[(size_t)(r0 + 8) * N + cc] = a4[2];
                }
                if (cc + 1 < N) {
                    P[(size_t)r0 * N + cc + 1]       = a4[1];
                    P[(size_t)(r0 + 8) * N + cc + 1] = a4[3];
                }
            }
        }
    }
}

// ---------------- split-K reduction + epilogue (float4) ----------------
template<int EM>
__global__ void reduce_epi(const float* __restrict__ Cpart,
    const float* __restrict__ bias, const float* __restrict__ resid,
    const float* __restrict__ e_aux, float* __restrict__ C,
    bf16* __restrict__ Chi, bf16* __restrict__ Clo, int M, int N, int S)
{
    int idx4 = (blockIdx.x * 256 + threadIdx.x) * 4;
    if (idx4 >= M * N) return;
    float4 s = make_float4(0.f, 0.f, 0.f, 0.f);
    for (int z = 0; z < S; z++) {
        float4 p = *(const float4*)(Cpart + (size_t)z * M * N + idx4);
        s.x += p.x; s.y += p.y; s.z += p.z; s.w += p.w;
    }
    int gm = idx4 / N, gn = idx4 - gm * N;
    float v0 = apply_epi<EM>(s.x, gm, gn,     bias, resid, e_aux, N);
    float v1 = apply_epi<EM>(s.y, gm, gn + 1, bias, resid, e_aux, N);
    float v2 = apply_epi<EM>(s.z, gm, gn + 2, bias, resid, e_aux, N);
    float v3 = apply_epi<EM>(s.w, gm, gn + 3, bias, resid, e_aux, N);
    if (C) *(float4*)(C + idx4) = make_float4(v0, v1, v2, v3);
    if (Chi) {
        *(uint2*)(Chi + idx4) = make_uint2(pk2(v0, v1), pk2(v2, v3));
        float h0 = __bfloat162float(__float2bfloat16(v0));
        float h1 = __bfloat162float(__float2bfloat16(v1));
        float h2 = __bfloat162float(__float2bfloat16(v2));
        float h3 = __bfloat162float(__float2bfloat16(v3));
        *(uint2*)(Clo + idx4) = make_uint2(pk2(v0 - h0, v1 - h1), pk2(v2 - h2, v3 - h3));
    }
}

// ---------------- block reduction helper ----------------
__device__ __forceinline__ float block_sum(float v, float* sred)
{
    __syncthreads();
#pragma unroll
    for (int o = 16; o; o >>= 1) v += __shfl_xor_sync(0xffffffffu, v, o);
    int w = threadIdx.x >> 5, l = threadIdx.x & 31;
    if (l == 0) sred[w] = v;
    __syncthreads();
    float t = (l < 8) ? sred[l] : 0.0f;
#pragma unroll
    for (int o = 4; o; o >>= 1) t += __shfl_xor_sync(0xffffffffu, t, o);
    if (threadIdx.x == 0) sred[0] = t;
    __syncthreads();
    return sred[0];
}

// ---------------- fused split-K reduce + bias + resid + LayerNorm ----------------
// one block per row (N = DMODEL = 1024, 256 threads x 4 contiguous cols)
__global__ void __launch_bounds__(256) reduce_ln(
    const float* __restrict__ Cpart, const float* __restrict__ bias,
    const float* __restrict__ resid,
    const float* __restrict__ g, const float* __restrict__ b,
    float* __restrict__ outF, bf16* __restrict__ hi, bf16* __restrict__ lo,
    int S)
{
    __shared__ float sred[32];
    int row  = blockIdx.x;
    int c0   = threadIdx.x * 4;
    int idx4 = row * DMODEL + c0;

    float4 s = make_float4(0.f, 0.f, 0.f, 0.f);
    for (int z = 0; z < S; z++) {
        float4 p = *(const float4*)(Cpart + (size_t)z * TLEN * DMODEL + idx4);
        s.x += p.x; s.y += p.y; s.z += p.z; s.w += p.w;
    }
    float4 bi = *(const float4*)(bias + c0);
    float4 rs = *(const float4*)(resid + idx4);
    float v[4] = { s.x + bi.x + rs.x, s.y + bi.y + rs.y,
                   s.z + bi.z + rs.z, s.w + bi.w + rs.w };

    float sum = v[0] + v[1] + v[2] + v[3];
    float mean = block_sum(sum, sred) * (1.0f / 1024.0f);
    float sq = 0.0f;
#pragma unroll
    for (int i = 0; i < 4; i++) { float d = v[i] - mean; sq += d * d; }
    float var  = block_sum(sq, sred) * (1.0f / 1024.0f);
    float rstd = rsqrtf(var + 1e-5f);

    float4 gg = *(const float4*)(g + c0);
    float4 bb = *(const float4*)(b + c0);
    float o0 = (v[0] - mean) * rstd * gg.x + bb.x;
    float o1 = (v[1] - mean) * rstd * gg.y + bb.y;
    float o2 = (v[2] - mean) * rstd * gg.z + bb.z;
    float o3 = (v[3] - mean) * rstd * gg.w + bb.w;

    if (outF) *(float4*)(outF + idx4) = make_float4(o0, o1, o2, o3);
    if (hi) {
        *(uint2*)(hi + idx4) = make_uint2(pk2(o0, o1), pk2(o2, o3));
        float h0 = __bfloat162float(__float2bfloat16(o0));
        float h1 = __bfloat162float(__float2bfloat16(o1));
        float h2 = __bfloat162float(__float2bfloat16(o2));
        float h3 = __bfloat162float(__float2bfloat16(o3));
        *(uint2*)(lo + idx4) = make_uint2(pk2(o0 - h0, o1 - h1), pk2(o2 - h2, o3 - h3));
    }
}

// ---------------- style ----------------
__global__ void style_k(const float* __restrict__ oh, const float* __restrict__ W,
                        float* __restrict__ st)
{
    int d = blockIdx.x * blockDim.x + threadIdx.x;
    if (d < DMODEL) {
        float s = 0.0f;
#pragma unroll
        for (int n = 0; n < 8; n++) s += oh[n] * W[d * 8 + n];
        st[d] = s;
    }
}

// ---------------- fused self-attention ----------------
#define ATT_BQ 16
#define ATT_KT 64
#define SPAD   516
#define QS_FLOATS (256 * 17)
#define SS_FLOATS (ATT_BQ * SPAD)
#define KV_FLOATS (256 * 68)
#define ATT_SMEM_BYTES ((QS_FLOATS + SS_FLOATS + KV_FLOATS) * 4)

__global__ void __launch_bounds__(256) attention_sa(const float* __restrict__ qkv,
                                                    bf16* __restrict__ ohi,
                                                    bf16* __restrict__ olo)
{
    extern __shared__ __align__(16) float sm[];
    float* Qs = sm;
    float* Ss = sm + QS_FLOATS;
    float* KV = sm + QS_FLOATS + SS_FLOATS;

    int h   = blockIdx.y;
    int q0  = blockIdx.x * ATT_BQ;
    int tid = threadIdx.x;
    float slope = exp2f(-2.0f * (float)(h + 1));

    for (int idx = tid; idx < ATT_BQ * 256; idx += 256) {
        int qi = idx >> 8, d = idx & 255;
        Qs[d * 17 + qi] = qkv[(size_t)(q0 + qi) * 3072 + h * 256 + d];
    }
    __syncthreads();

    int qmax = q0 + ATT_BQ - 1;
    int qi   = tid >> 4;

    {
        int kk0 = (tid & 15) * 4;
        for (int s0 = 0; s0 < TLEN; s0 += ATT_KT) {
            if (s0 > qmax) {
                for (int idx = tid; idx < ATT_BQ * ATT_KT; idx += 256) {
                    int rr = idx >> 6, cc = idx & 63;
                    Ss[rr * SPAD + s0 + cc] = -1e30f;
                }
                continue;
            }
            for (int idx = tid; idx < ATT_KT * 256; idx += 256) {
                int kk = idx >> 8, d = idx & 255;
                KV[d * 68 + kk] = qkv[(size_t)(s0 + kk) * 3072 + 1024 + h * 256 + d];
            }
            __syncthreads();
            float a0 = 0.f, a1 = 0.f, a2 = 0.f, a3 = 0.f;
#pragma unroll 4
            for (int d = 0; d < 256; d++) {
                float  qv = Qs[d * 17 + qi];
                float4 kv = *(const float4*)&KV[d * 68 + kk0];
                a0 = fmaf(qv, kv.x, a0);
                a1 = fmaf(qv, kv.y, a1);
                a2 = fmaf(qv, kv.z, a2);
                a3 = fmaf(qv, kv.w, a3);
            }
            int i  = q0 + qi;
            int jb = s0 + kk0;
            float accs[4] = {a0, a1, a2, a3};
#pragma unroll
            for (int c = 0; c < 4; c++) {
                int jj = jb + c;
                float mv = (jj > i) ? -1e30f : (-slope * (float)((i - jj) / 25));
                Ss[qi * SPAD + jj] = accs[c] * 0.0625f + mv;
            }
            __syncthreads();
        }
    }
    __syncthreads();

    {
        int warp = tid >> 5, lane = tid & 31;
        for (int rr = warp; rr < ATT_BQ; rr += 8) {
            float mx = -1e30f;
            for (int jj = lane; jj < TLEN; jj += 32) mx = fmaxf(mx, Ss[rr * SPAD + jj]);
#pragma unroll
            for (int o = 16; o; o >>= 1) mx = fmaxf(mx, __shfl_xor_sync(0xffffffffu, mx, o));
            float sum = 0.0f;
            for (int jj = lane; jj < TLEN; jj += 32) {
                float e = expf(Ss[rr * SPAD + jj] - mx);
                Ss[rr * SPAD + jj] = e;
                sum += e;
            }
#pragma unroll
            for (int o = 16; o; o >>= 1) sum += __shfl_xor_sync(0xffffffffu, sum, o);
            float inv = 1.0f / sum;
            for (int jj = lane; jj < TLEN; jj += 32) Ss[rr * SPAD + jj] *= inv;
        }
    }
    __syncthreads();

    float acc[16];
#pragma unroll
    for (int i = 0; i < 16; i++) acc[i] = 0.0f;
    int d0 = (tid & 15) * 16;

    for (int s0 = 0; s0 <= qmax; s0 += ATT_KT) {
        for (int idx = tid; idx < ATT_KT * 256; idx += 256) {
            int kk = idx >> 8, d = idx & 255;
            KV[kk * 256 + d] = qkv[(size_t)(s0 + kk) * 3072 + 2048 + h * 256 + d];
        }
        __syncthreads();
        for (int kk = 0; kk < ATT_KT; kk++) {
            float a = Ss[qi * SPAD + s0 + kk];
            const float4* vp = (const float4*)&KV[kk * 256 + d0];
            float4 v0 = vp[0], v1 = vp[1], v2 = vp[2], v3 = vp[3];
            acc[0]  = fmaf(a, v0.x, acc[0]);  acc[1]  = fmaf(a, v0.y, acc[1]);
            acc[2]  = fmaf(a, v0.z, acc[2]);  acc[3]  = fmaf(a, v0.w, acc[3]);
            acc[4]  = fmaf(a, v1.x, acc[4]);  acc[5]  = fmaf(a, v1.y, acc[5]);
            acc[6]  = fmaf(a, v1.z, acc[6]);  acc[7]  = fmaf(a, v1.w, acc[7]);
            acc[8]  = fmaf(a, v2.x, acc[8]);  acc[9]  = fmaf(a, v2.y, acc[9]);
            acc[10] = fmaf(a, v2.z, acc[10]); acc[11] = fmaf(a, v2.w, acc[11]);
            acc[12] = fmaf(a, v3.x, acc[12]); acc[13] = fmaf(a, v3.y, acc[13]);
            acc[14] = fmaf(a, v3.z, acc[14]); acc[15] = fmaf(a, v3.w, acc[15]);
        }
        __syncthreads();
    }
#pragma unroll
    for (int c = 0; c < 16; c++)
        split_write(ohi, olo, (size_t)(q0 + qi) * 1024 + h * 256 + d0 + c, acc[c]);
}

// ---------------- launcher ----------------
extern "C" void kernel_launch(void* const* d_in, const int* in_sizes, int n_in,
                              void* d_out, int out_size)
{
    const float* audio   = (const float*)d_in[0];
    const float* vertice = (const float*)d_in[1];
    const float* tmpl    = (const float*)d_in[2];
    const float* one_hot = (const float*)d_in[3];
    const float* W_af    = (const float*)d_in[4];
    const float* b_af    = (const float*)d_in[5];
    const float* W_vm    = (const float*)d_in[6];
    const float* b_vm    = (const float*)d_in[7];
    const float* W_obj   = (const float*)d_in[8];
    const float* Wqkv_sa = (const float*)d_in[9];
    const float* bqkv_sa = (const float*)d_in[10];
    const float* Wo_sa   = (const float*)d_in[11];
    const float* bo_sa   = (const float*)d_in[12];
    const float* Wqkv_ca = (const float*)d_in[13];
    const float* bqkv_ca = (const float*)d_in[14];
    const float* Wo_ca   = (const float*)d_in[15];
    const float* bo_ca   = (const float*)d_in[16];
    const float* W1      = (const float*)d_in[17];
    const float* b1      = (const float*)d_in[18];
    const float* W2      = (const float*)d_in[19];
    const float* b2      = (const float*)d_in[20];
    const float* g1      = (const float*)d_in[21];
    const float* be1     = (const float*)d_in[22];
    const float* g2      = (const float*)d_in[23];
    const float* be2     = (const float*)d_in[24];
    const float* g3      = (const float*)d_in[25];
    const float* be3     = (const float*)d_in[26];
    const float* W_vr    = (const float*)d_in[27];
    const float* b_vr    = (const float*)d_in[28];
    float* out = (float*)d_out;

    float *style, *x, *y, *qkv, *part;
    cudaGetSymbolAddress((void**)&style, g_style);
    cudaGetSymbolAddress((void**)&x,     g_x);
    cudaGetSymbolAddress((void**)&y,     g_y);
    cudaGetSymbolAddress((void**)&qkv,   g_qkv);
    cudaGetSymbolAddress((void**)&part,  g_part);

#define SYM(p, s) bf16* p; cudaGetSymbolAddress((void**)&p, s)
    SYM(Waf_h, g_Waf_h);  SYM(Waf_l, g_Waf_l);
    SYM(Wvm_h, g_Wvm_h);  SYM(Wvm_l, g_Wvm_l);
    SYM(Wqkv_h, g_Wqkv_h); SYM(Wqkv_l, g_Wqkv_l);
    SYM(Wosa_h, g_Wosa_h); SYM(Wosa_l, g_Wosa_l);
    SYM(Wvca_h, g_Wvca_h); SYM(Wvca_l, g_Wvca_l);
    SYM(Woca_h, g_Woca_h); SYM(Woca_l, g_Woca_l);
    SYM(W1_h, g_W1_h);    SYM(W1_l, g_W1_l);
    SYM(W2_h, g_W2_h);    SYM(W2_l, g_W2_l);
    SYM(Wvr_h, g_Wvr_h);  SYM(Wvr_l, g_Wvr_l);
    SYM(aud_h, g_aud_h);  SYM(aud_l, g_aud_l);
    SYM(vin_h, g_vin_h);  SYM(vin_l, g_vin_l);
    SYM(hid_h, g_hid_h);  SYM(hid_l, g_hid_l);
    SYM(xa_h, g_xa_h);    SYM(xa_l, g_xa_l);
    SYM(x2_h, g_x2_h);    SYM(x2_l, g_x2_l);
    SYM(y2_h, g_y2_h);    SYM(y2_l, g_y2_l);
    SYM(attn_h, g_attn_h); SYM(attn_l, g_attn_l);
    SYM(vca_h, g_vca_h);  SYM(vca_l, g_vca_l);
    SYM(ff_h, g_ff_h);    SYM(ff_l, g_ff_l);
#undef SYM

    cudaFuncSetAttribute(attention_sa,
        cudaFuncAttributeMaxDynamicSharedMemorySize, ATT_SMEM_BYTES);
    cudaFuncSetAttribute(mma_gemm2<0>,
        cudaFuncAttributeMaxDynamicSharedMemorySize, GEMM_SMEM_BYTES);
    cudaFuncSetAttribute(mma_gemm2<4>,
        cudaFuncAttributeMaxDynamicSharedMemorySize, GEMM_SMEM_BYTES);

    const int M = TLEN;

    // ---- single merged conversion launch ----
    {
        ConvJobs J;
        J.tmpl = tmpl;
        const float* srcs[NJOBS] = { W_af, audio, W_vm, vertice, Wqkv_sa,
                                     Wo_sa, Wqkv_ca + (size_t)2048*DMODEL, Wo_ca,
                                     W1, W2, W_vr };
        bf16* his[NJOBS] = { Waf_h, aud_h, Wvm_h, vin_h, Wqkv_h, Wosa_h, Wvca_h,
                             Woca_h, W1_h, W2_h, Wvr_h };
        bf16* los[NJOBS] = { Waf_l, aud_l, Wvm_l, vin_l, Wqkv_l, Wosa_l, Wvca_l,
                             Woca_l, W1_l, W2_l, Wvr_l };
        int Ks[NJOBS]    = { AUDDIM, AUDDIM, V3DIM, V3DIM, DMODEL, DMODEL, DMODEL,
                             DMODEL, DMODEL, DFFDIM, DMODEL };
        int Kps[NJOBS]   = { AUDDIM, AUDDIM, KVPAD, KVPAD, DMODEL, DMODEL, DMODEL,
                             DMODEL, DMODEL, DFFDIM, DMODEL };
        int rows[NJOBS]  = { DMODEL, TLEN, DMODEL, TLEN, 3*DMODEL, DMODEL, DMODEL,
                             DMODEL, DFFDIM, DMODEL, V3DIM };
        int modes[NJOBS] = { 0, 0, 0, 1, 0, 0, 0, 0, 0, 0, 0 };
        int nb = 0;
        for (int t = 0; t < NJOBS; t++) {
            J.src[t] = srcs[t]; J.hi[t] = his[t]; J.lo[t] = los[t];
            J.K[t] = Ks[t]; J.Kpad[t] = Kps[t]; J.mode[t] = modes[t];
            J.total[t] = (long)rows[t] * Kps[t];
            nb += (int)((J.total[t] + 4095) / 4096);
            J.blk_end[t] = nb;
        }
        conv_all<<<nb, 256>>>(J);
    }
    style_k<<<4, 256>>>(one_hot, W_obj, style);

    // ---- hidden = audio @ W_af^T + b_af ----
    mma_gemm2<0><<<dim3(8,4,4), 256, GEMM_SMEM_BYTES>>>(
        aud_h, aud_l, Waf_h, Waf_l, nullptr, nullptr,
        nullptr, part, M, DMODEL, AUDDIM, 24, 4);
    reduce_epi<0><<<(M*DMODEL/4+255)/256, 256>>>(part, b_af, nullptr, nullptr,
        nullptr, hid_h, hid_l, M, DMODEL, 4);

    // ---- x = vin @ W_vm^T + b_vm + style + PE ----
    mma_gemm2<0><<<dim3(8,4,9), 256, GEMM_SMEM_BYTES>>>(
        vin_h, vin_l, Wvm_h, Wvm_l, nullptr, nullptr,
        nullptr, part, M, DMODEL, KVPAD, 472, 9);
    reduce_epi<3><<<(M*DMODEL/4+255)/256, 256>>>(part, b_vm, nullptr, style,
        x, xa_h, xa_l, M, DMODEL, 9);

    // ---- qkv ----
    mma_gemm2<0><<<dim3(24,4,2), 256, GEMM_SMEM_BYTES>>>(
        xa_h, xa_l, Wqkv_h, Wqkv_l, nullptr, nullptr,
        nullptr, part, M, 3*DMODEL, DMODEL, 32, 2);
    reduce_epi<0><<<(M*3*DMODEL/4+255)/256, 256>>>(part, bqkv_sa, nullptr, nullptr,
        qkv, nullptr, nullptr, M, 3*DMODEL, 2);

    attention_sa<<<dim3(TLEN/ATT_BQ, NHEAD), 256, ATT_SMEM_BYTES>>>(qkv, attn_h, attn_l);

    // ---- y = LN1(x + attn @ Wo_sa^T + bo_sa)  [fused reduce+LN] ----
    mma_gemm2<0><<<dim3(8,4,4), 256, GEMM_SMEM_BYTES>>>(
        attn_h, attn_l, Wosa_h, Wosa_l, nullptr, nullptr,
        nullptr, part, M, DMODEL, DMODEL, 32, 4);
    reduce_ln<<<M, 256>>>(part, bo_sa, x, g1, be1, y, nullptr, nullptr, 4);

    // ---- cross-attn (diagonal): vca ; x = LN2(y + vca @ Wo_ca^T + bo_ca) ----
    mma_gemm2<0><<<dim3(8,4,4), 256, GEMM_SMEM_BYTES>>>(
        hid_h, hid_l, Wvca_h, Wvca_l, nullptr, nullptr,
        nullptr, part, M, DMODEL, DMODEL, 32, 4);
    reduce_epi<0><<<(M*DMODEL/4+255)/256, 256>>>(part, bqkv_ca + 2048, nullptr, nullptr,
        nullptr, vca_h, vca_l, M, DMODEL, 4);
    mma_gemm2<0><<<dim3(8,4,4), 256, GEMM_SMEM_BYTES>>>(
        vca_h, vca_l, Woca_h, Woca_l, nullptr, nullptr,
        nullptr, part, M, DMODEL, DMODEL, 32, 4);
    reduce_ln<<<M, 256>>>(part, bo_ca, y, g2, be2, x, x2_h, x2_l, 4);

    // ---- FFN ----
    mma_gemm2<0><<<dim3(16,4,2), 256, GEMM_SMEM_BYTES>>>(
        x2_h, x2_l, W1_h, W1_l, nullptr, nullptr,
        nullptr, part, M, DFFDIM, DMODEL, 32, 2);
    reduce_epi<1><<<(M*DFFDIM/4+255)/256, 256>>>(part, b1, nullptr, nullptr,
        nullptr, ff_h, ff_l, M, DFFDIM, 2);
    mma_gemm2<0><<<dim3(8,4,4), 256, GEMM_SMEM_BYTES>>>(
        ff_h, ff_l, W2_h, W2_l, nullptr, nullptr,
        nullptr, part, M, DMODEL, DFFDIM, 64, 4);
    reduce_ln<<<M, 256>>>(part, b2, x, g3, be3, nullptr, y2_h, y2_l, 4);

    // ---- out = y2 @ W_vr^T + b_vr + template ----
    mma_gemm2<4><<<dim3((V3DIM+127)/128, 4, 1), 256, GEMM_SMEM_BYTES>>>(
        y2_h, y2_l, Wvr_h, Wvr_l, b_vr, tmpl,
        out, nullptr, M, V3DIM, DMODEL, 32, 1);
}

// round 16
// speedup vs baseline: 1.9694x; 1.0069x over previous
#include <cuda_runtime.h>
#include <cuda_bf16.h>
#include <math.h>
#include <stdint.h>

typedef __nv_bfloat16 bf16;

// ---------------- problem constants ----------------
#define DMODEL 1024
#define NHEAD  4
#define HDIM   256
#define TLEN   512
#define V3DIM  15069
#define KVPAD  15104
#define DFFDIM 2048
#define AUDDIM 768

// ---------------- fp32 scratch ----------------
__device__ float g_style [DMODEL];
__device__ float g_x     [TLEN * DMODEL];
__device__ float g_y     [TLEN * DMODEL];
__device__ float g_qkv   [TLEN * 3 * DMODEL];
__device__ float g_part  [12 * TLEN * DMODEL];

// ---------------- bf16 hi/lo buffers ----------------
__device__ bf16 g_Waf_h [DMODEL * AUDDIM],  g_Waf_l [DMODEL * AUDDIM];
__device__ bf16 g_Wvm_h [DMODEL * KVPAD],   g_Wvm_l [DMODEL * KVPAD];
__device__ bf16 g_Wqkv_h[3 * DMODEL * DMODEL], g_Wqkv_l[3 * DMODEL * DMODEL];
__device__ bf16 g_Wosa_h[DMODEL * DMODEL],  g_Wosa_l[DMODEL * DMODEL];
__device__ bf16 g_Wvca_h[DMODEL * DMODEL],  g_Wvca_l[DMODEL * DMODEL];
__device__ bf16 g_Woca_h[DMODEL * DMODEL],  g_Woca_l[DMODEL * DMODEL];
__device__ bf16 g_W1_h  [DFFDIM * DMODEL],  g_W1_l  [DFFDIM * DMODEL];
__device__ bf16 g_W2_h  [DMODEL * DFFDIM],  g_W2_l  [DMODEL * DFFDIM];
__device__ bf16 g_Wvr_h [V3DIM * DMODEL],   g_Wvr_l [V3DIM * DMODEL];

__device__ bf16 g_aud_h [TLEN * AUDDIM],  g_aud_l [TLEN * AUDDIM];
__device__ bf16 g_vin_h [TLEN * KVPAD],   g_vin_l [TLEN * KVPAD];
__device__ bf16 g_hid_h [TLEN * DMODEL],  g_hid_l [TLEN * DMODEL];
__device__ bf16 g_xa_h  [TLEN * DMODEL],  g_xa_l  [TLEN * DMODEL];
__device__ bf16 g_x2_h  [TLEN * DMODEL],  g_x2_l  [TLEN * DMODEL];
__device__ bf16 g_y2_h  [TLEN * DMODEL],  g_y2_l  [TLEN * DMODEL];
__device__ bf16 g_attn_h[TLEN * DMODEL],  g_attn_l[TLEN * DMODEL];
__device__ bf16 g_vca_h [TLEN * DMODEL],  g_vca_l [TLEN * DMODEL];
__device__ bf16 g_ff_h  [TLEN * DFFDIM],  g_ff_l  [TLEN * DFFDIM];

// ---------------- helpers ----------------
__device__ __forceinline__ uint32_t smem_u32(const void* p){
    uint32_t a;
    asm("{ .reg .u64 t; cvta.to.shared.u64 t, %1; cvt.u32.u64 %0, t; }" : "=r"(a) : "l"(p));
    return a;
}
__device__ __forceinline__ void cp_async16(uint32_t dst, const void* src, uint32_t sz){
    asm volatile("cp.async.cg.shared.global [%0], [%1], 16, %2;" :: "r"(dst), "l"(src), "r"(sz));
}
__device__ __forceinline__ void cp_commit(){
    asm volatile("cp.async.commit_group;" ::: "memory");
}
__device__ __forceinline__ void cp_wait(int allow){
    if (allow <= 0)      asm volatile("cp.async.wait_group 0;" ::: "memory");
    else                 asm volatile("cp.async.wait_group 1;" ::: "memory");
}
__device__ __forceinline__ void split_write(bf16* hi, bf16* lo, size_t o, float v){
    bf16 h = __float2bfloat16(v);
    hi[o] = h;
    lo[o] = __float2bfloat16(v - __bfloat162float(h));
}
__device__ __forceinline__ uint32_t pk2(float a, float b){
    __nv_bfloat162 t(__float2bfloat16(a), __float2bfloat16(b));
    uint32_t u; memcpy(&u, &t, 4); return u;
}

// ---------------- epilogue ----------------
// EM: 0=+bias ; 1=+bias,relu ; 2=+bias,+resid ; 3=+bias,+style,+PE ; 4=+bias,+template[n]
template<int EM>
__device__ __forceinline__ float apply_epi(float v, int gm, int gn,
    const float* bias, const float* resid, const float* e_aux, int N)
{
    v += bias[gn];
    if (EM == 1) v = fmaxf(v, 0.0f);
    if (EM == 2) v += resid[(size_t)gm * N + gn];
    if (EM == 3) {
        v += e_aux[gn];
        int   p   = gm % 25;
        int   e   = gn & ~1;
        float dv  = expf((float)e * (-9.210340371976184f / 1024.0f));
        float ang = (float)p * dv;
        v += (gn & 1) ? cosf(ang) : sinf(ang);
    }
    if (EM == 4) v += e_aux[gn];
    return v;
}

// ---------------- merged conversion kernel: 16 elems/thread ----------------
#define NJOBS 11
struct ConvJobs {
    const float* src[NJOBS];
    bf16* hi[NJOBS];
    bf16* lo[NJOBS];
    int   K[NJOBS];
    int   Kpad[NJOBS];
    long  total[NJOBS];
    int   mode[NJOBS];
    int   blk_end[NJOBS];
    const float* tmpl;
};

__global__ void __launch_bounds__(256) conv_all(ConvJobs J)
{
    int b = blockIdx.x;
    int j = 0;
#pragma unroll
    for (int t = 0; t < NJOBS; t++) if (b >= J.blk_end[t]) j = t + 1;
    int b0    = (j == 0) ? 0 : J.blk_end[j - 1];
    long e0   = (long)(b - b0) * 4096 + threadIdx.x * 4;
    int Kpad  = J.Kpad[j], K = J.K[j];
    long tot  = J.total[j];
    const float* src = J.src[j];
    int mode  = J.mode[j];
    bf16* hi  = J.hi[j];
    bf16* lo  = J.lo[j];

#pragma unroll
    for (int q = 0; q < 4; q++) {
        long e = e0 + q * 1024;
        if (e >= tot) break;
        int row = (int)(e / Kpad);
        int kp  = (int)(e - (long)row * Kpad);
        float v[4];
        if (mode == 1) {
            if (row == 0) { v[0] = v[1] = v[2] = v[3] = 0.0f; }
            else {
                const float* s = src + (size_t)(row - 1) * K;
#pragma unroll
                for (int i = 0; i < 4; i++) {
                    int k = kp + i;
                    v[i] = (k < K) ? s[k] - J.tmpl[k] : 0.0f;
                }
            }
        } else {
            const float* s = src + (size_t)row * K;
#pragma unroll
            for (int i = 0; i < 4; i++) {
                int k = kp + i;
                v[i] = (k < K) ? s[k] : 0.0f;
            }
        }
        float h0 = __bfloat162float(__float2bfloat16(v[0]));
        float h1 = __bfloat162float(__float2bfloat16(v[1]));
        float h2 = __bfloat162float(__float2bfloat16(v[2]));
        float h3 = __bfloat162float(__float2bfloat16(v[3]));
        size_t o = (size_t)row * Kpad + kp;
        *(uint2*)(hi + o) = make_uint2(pk2(h0, h1), pk2(h2, h3));
        *(uint2*)(lo + o) = make_uint2(pk2(v[0] - h0, v[1] - h1),
                                       pk2(v[2] - h2, v[3] - h3));
    }
}

// ---------------- mma.sync GEMM (champion) ----------------
__device__ __forceinline__ void mma16816(float* c,
    uint32_t a0, uint32_t a1, uint32_t a2, uint32_t a3,
    uint32_t b0, uint32_t b1)
{
    asm volatile("mma.sync.aligned.m16n8k16.row.col.f32.bf16.bf16.f32 "
        "{%0,%1,%2,%3}, {%4,%5,%6,%7}, {%8,%9}, {%0,%1,%2,%3};"
        : "+f"(c[0]), "+f"(c[1]), "+f"(c[2]), "+f"(c[3])
        : "r"(a0), "r"(a1), "r"(a2), "r"(a3), "r"(b0), "r"(b1));
}

#define ROWB    80
#define TILE_SM (128 * ROWB)
#define STG_SM  (4 * TILE_SM)
#define NSTAGE  2
#define GEMM_SMEM_BYTES (NSTAGE * STG_SM)

__device__ __forceinline__ void compute_chunk(const char* base, int wm, int wn,
                                              int lane, float (&acc)[4][4][4])
{
    const char* sAh = base;
    const char* sAl = base + TILE_SM;
    const char* sBh = base + 2 * TILE_SM;
    const char* sBl = base + 3 * TILE_SM;
    int l4 = lane >> 2, lt = (lane & 3) * 4;

#pragma unroll
    for (int ks = 0; ks < 2; ks++) {
        int kb = ks * 32 + lt;
        uint32_t bh[4][2], bl[4][2];
#pragma unroll
        for (int nt = 0; nt < 4; nt++) {
            int nr = wn * 32 + nt * 8 + l4;
            const char* p = sBh + nr * ROWB + kb;
            bh[nt][0] = *(const uint32_t*)p;
            bh[nt][1] = *(const uint32_t*)(p + 16);
            const char* q = sBl + nr * ROWB + kb;
            bl[nt][0] = *(const uint32_t*)q;
            bl[nt][1] = *(const uint32_t*)(q + 16);
        }
#pragma unroll
        for (int mt = 0; mt < 4; mt++) {
            int r0 = wm * 64 + mt * 16 + l4;
            const char* p = sAh + r0 * ROWB + kb;
            uint32_t ah0 = *(const uint32_t*)p;
            uint32_t ah1 = *(const uint32_t*)(p + 8 * ROWB);
            uint32_t ah2 = *(const uint32_t*)(p + 16);
            uint32_t ah3 = *(const uint32_t*)(p + 8 * ROWB + 16);
            const char* q = sAl + r0 * ROWB + kb;
            uint32_t al0 = *(const uint32_t*)q;
            uint32_t al1 = *(const uint32_t*)(q + 8 * ROWB);
            uint32_t al2 = *(const uint32_t*)(q + 16);
            uint32_t al3 = *(const uint32_t*)(q + 8 * ROWB + 16);
#pragma unroll
            for (int nt = 0; nt < 4; nt++)
                mma16816(acc[mt][nt], ah0, ah1, ah2, ah3, bh[nt][0], bh[nt][1]);
#pragma unroll
            for (int nt = 0; nt < 4; nt++)
                mma16816(acc[mt][nt], ah0, ah1, ah2, ah3, bl[nt][0], bl[nt][1]);
#pragma unroll
            for (int nt = 0; nt < 4; nt++)
                mma16816(acc[mt][nt], al0, al1, al2, al3, bh[nt][0], bh[nt][1]);
        }
    }
}

__device__ __forceinline__ void stage_copy(uint32_t sb32, int stage,
    const bf16* __restrict__ Ah, const bf16* __restrict__ Al,
    const bf16* __restrict__ Bh, const bf16* __restrict__ Bl,
    int bm, int bn, int N, int Kpad, int kk, int tid)
{
    uint32_t st = sb32 + stage * STG_SM;
#pragma unroll
    for (int c = 0; c < 8; c++) {
        int g    = c * 256 + tid;
        int tile = g >> 9;
        int rem  = g & 511;
        int row  = rem >> 2, col = rem & 3;
        uint32_t dst = st + tile * TILE_SM + row * ROWB + col * 16;
        const bf16* base;
        int rowg; uint32_t sz = 16;
        if (tile < 2) { base = tile ? Al : Ah; rowg = bm + row; }
        else {
            base = (tile == 3) ? Bl : Bh; rowg = bn + row;
            if (rowg >= N) { rowg = 0; sz = 0; }
        }
        cp_async16(dst, base + (size_t)rowg * Kpad + kk + col * 8, sz);
    }
}

template<int EM>
__global__ void __launch_bounds__(256, 2) mma_gemm2(
    const bf16* __restrict__ Ah, const bf16* __restrict__ Al,
    const bf16* __restrict__ Bh, const bf16* __restrict__ Bl,
    const float* __restrict__ bias, const float* __restrict__ e_aux,
    float* __restrict__ C, float* __restrict__ Cpart,
    int M, int N, int Kpad, int nchunks, int nsplit)
{
    extern __shared__ __align__(16) char smem[];
    uint32_t sb32 = smem_u32(smem);
    int tid  = threadIdx.x;
    int wid  = tid >> 5, lane = tid & 31;
    int wm   = wid >> 2, wn = wid & 3;
    int bm   = blockIdx.y * 128, bn = blockIdx.x * 128;
    int cpz  = (nchunks + nsplit - 1) / nsplit;
    int c0   = blockIdx.z * cpz;
    int c1   = min(nchunks, c0 + cpz);
    int nloc = c1 - c0;

    float acc[4][4][4];
#pragma unroll
    for (int a = 0; a < 4; a++)
#pragma unroll
        for (int b = 0; b < 4; b++)
#pragma unroll
            for (int c = 0; c < 4; c++) acc[a][b][c] = 0.0f;

    int npre = min(NSTAGE, nloc);
    for (int s = 0; s < npre; s++) {
        stage_copy(sb32, s, Ah, Al, Bh, Bl, bm, bn, N, Kpad, (c0 + s) * 32, tid);
        cp_commit();
    }

    for (int j = 0; j < nloc; j++) {
        cp_wait(min(nloc - 1 - j, NSTAGE - 1));
        __syncthreads();
        compute_chunk(smem + (j % NSTAGE) * STG_SM, wm, wn, lane, acc);
        __syncthreads();
        if (j + NSTAGE < nloc) {
            stage_copy(sb32, j % NSTAGE, Ah, Al, Bh, Bl, bm, bn, N, Kpad,
                       (c0 + j + NSTAGE) * 32, tid);
            cp_commit();
        }
    }

    int l4 = lane >> 2, lt = lane & 3;
#pragma unroll
    for (int mt = 0; mt < 4; mt++) {
#pragma unroll
        for (int nt = 0; nt < 4; nt++) {
            int r0 = bm + wm * 64 + mt * 16 + l4;
            int cc = bn + wn * 32 + nt * 8 + lt * 2;
            float* a4 = acc[mt][nt];
            if (nsplit == 1) {
                if (cc < N) {
                    C[(size_t)r0 * N + cc]       = apply_epi<EM>(a4[0], r0, cc, bias, nullptr, e_aux, N);
                    C[(size_t)(r0 + 8) * N + cc] = apply_epi<EM>(a4[2], r0 + 8, cc, bias, nullptr, e_aux, N);
                }
                if (cc + 1 < N) {
                    C[(size_t)r0 * N + cc + 1]       = apply_epi<EM>(a4[1], r0, cc + 1, bias, nullptr, e_aux, N);
                    C[(size_t)(r0 + 8) * N + cc + 1] = apply_epi<EM>(a4[3], r0 + 8, cc + 1, bias, nullptr, e_aux, N);
                }
            } else {
                float* P = Cpart + (size_t)blockIdx.z * M * N;
                if (cc < N) {
                    P[(size_t)r0 * N + cc]       = a4[0];
                    P[(size_t)(r0 + 8) * N + cc] = a4[2];
                }
                if (cc + 1 < N) {
                    P[(size_t)r0 * N + cc + 1]       = a4[1];
                    P[(size_t)(r0 + 8) * N + cc + 1] = a4[3];
                }
            }
        }
    }
}

// ---------------- split-K reduction + epilogue (float4) ----------------
template<int EM>
__global__ void reduce_epi(const float* __restrict__ Cpart,
    const float* __restrict__ bias, const float* __restrict__ resid,
    const float* __restrict__ e_aux, float* __restrict__ C,
    bf16* __restrict__ Chi, bf16* __restrict__ Clo, int M, int N, int S)
{
    int idx4 = (blockIdx.x * 256 + threadIdx.x) * 4;
    if (idx4 >= M * N) return;
    float4 s = make_float4(0.f, 0.f, 0.f, 0.f);
    for (int z = 0; z < S; z++) {
        float4 p = *(const float4*)(Cpart + (size_t)z * M * N + idx4);
        s.x += p.x; s.y += p.y; s.z += p.z; s.w += p.w;
    }
    int gm = idx4 / N, gn = idx4 - gm * N;
    float v0 = apply_epi<EM>(s.x, gm, gn,     bias, resid, e_aux, N);
    float v1 = apply_epi<EM>(s.y, gm, gn + 1, bias, resid, e_aux, N);
    float v2 = apply_epi<EM>(s.z, gm, gn + 2, bias, resid, e_aux, N);
    float v3 = apply_epi<EM>(s.w, gm, gn + 3, bias, resid, e_aux, N);
    if (C) *(float4*)(C + idx4) = make_float4(v0, v1, v2, v3);
    if (Chi) {
        *(uint2*)(Chi + idx4) = make_uint2(pk2(v0, v1), pk2(v2, v3));
        float h0 = __bfloat162float(__float2bfloat16(v0));
        float h1 = __bfloat162float(__float2bfloat16(v1));
        float h2 = __bfloat162float(__float2bfloat16(v2));
        float h3 = __bfloat162float(__float2bfloat16(v3));
        *(uint2*)(Clo + idx4) = make_uint2(pk2(v0 - h0, v1 - h1), pk2(v2 - h2, v3 - h3));
    }
}

// ---------------- block reduction helper ----------------
__device__ __forceinline__ float block_sum(float v, float* sred)
{
    __syncthreads();
#pragma unroll
    for (int o = 16; o; o >>= 1) v += __shfl_xor_sync(0xffffffffu, v, o);
    int w = threadIdx.x >> 5, l = threadIdx.x & 31;
    if (l == 0) sred[w] = v;
    __syncthreads();
    float t = (l < 8) ? sred[l] : 0.0f;
#pragma unroll
    for (int o = 4; o; o >>= 1) t += __shfl_xor_sync(0xffffffffu, t, o);
    if (threadIdx.x == 0) sred[0] = t;
    __syncthreads();
    return sred[0];
}

// ---------------- fused split-K reduce + bias + resid + LayerNorm ----------------
__global__ void __launch_bounds__(256) reduce_ln(
    const float* __restrict__ Cpart, const float* __restrict__ bias,
    const float* __restrict__ resid,
    const float* __restrict__ g, const float* __restrict__ b,
    float* __restrict__ outF, bf16* __restrict__ hi, bf16* __restrict__ lo,
    int S)
{
    __shared__ float sred[32];
    int row  = blockIdx.x;
    int c0   = threadIdx.x * 4;
    int idx4 = row * DMODEL + c0;

    float4 s = make_float4(0.f, 0.f, 0.f, 0.f);
    for (int z = 0; z < S; z++) {
        float4 p = *(const float4*)(Cpart + (size_t)z * TLEN * DMODEL + idx4);
        s.x += p.x; s.y += p.y; s.z += p.z; s.w += p.w;
    }
    float4 bi = *(const float4*)(bias + c0);
    float4 rs = *(const float4*)(resid + idx4);
    float v[4] = { s.x + bi.x + rs.x, s.y + bi.y + rs.y,
                   s.z + bi.z + rs.z, s.w + bi.w + rs.w };

    float sum = v[0] + v[1] + v[2] + v[3];
    float mean = block_sum(sum, sred) * (1.0f / 1024.0f);
    float sq = 0.0f;
#pragma unroll
    for (int i = 0; i < 4; i++) { float d = v[i] - mean; sq += d * d; }
    float var  = block_sum(sq, sred) * (1.0f / 1024.0f);
    float rstd = rsqrtf(var + 1e-5f);

    float4 gg = *(const float4*)(g + c0);
    float4 bb = *(const float4*)(b + c0);
    float o0 = (v[0] - mean) * rstd * gg.x + bb.x;
    float o1 = (v[1] - mean) * rstd * gg.y + bb.y;
    float o2 = (v[2] - mean) * rstd * gg.z + bb.z;
    float o3 = (v[3] - mean) * rstd * gg.w + bb.w;

    if (outF) *(float4*)(outF + idx4) = make_float4(o0, o1, o2, o3);
    if (hi) {
        *(uint2*)(hi + idx4) = make_uint2(pk2(o0, o1), pk2(o2, o3));
        float h0 = __bfloat162float(__float2bfloat16(o0));
        float h1 = __bfloat162float(__float2bfloat16(o1));
        float h2 = __bfloat162float(__float2bfloat16(o2));
        float h3 = __bfloat162float(__float2bfloat16(o3));
        *(uint2*)(lo + idx4) = make_uint2(pk2(o0 - h0, o1 - h1), pk2(o2 - h2, o3 - h3));
    }
}

// ---------------- style ----------------
__global__ void style_k(const float* __restrict__ oh, const float* __restrict__ W,
                        float* __restrict__ st)
{
    int d = blockIdx.x * blockDim.x + threadIdx.x;
    if (d < DMODEL) {
        float s = 0.0f;
#pragma unroll
        for (int n = 0; n < 8; n++) s += oh[n] * W[d * 8 + n];
        st[d] = s;
    }
}

// ---------------- fused self-attention ----------------
#define ATT_BQ 16
#define ATT_KT 64
#define SPAD   516
#define QS_FLOATS (256 * 17)
#define SS_FLOATS (ATT_BQ * SPAD)
#define KV_FLOATS (256 * 68)
#define ATT_SMEM_BYTES ((QS_FLOATS + SS_FLOATS + KV_FLOATS) * 4)

__global__ void __launch_bounds__(256) attention_sa(const float* __restrict__ qkv,
                                                    bf16* __restrict__ ohi,
                                                    bf16* __restrict__ olo)
{
    extern __shared__ __align__(16) float sm[];
    float* Qs = sm;
    float* Ss = sm + QS_FLOATS;
    float* KV = sm + QS_FLOATS + SS_FLOATS;

    int h   = blockIdx.y;
    int q0  = blockIdx.x * ATT_BQ;
    int tid = threadIdx.x;
    float slope = exp2f(-2.0f * (float)(h + 1));

    for (int idx = tid; idx < ATT_BQ * 256; idx += 256) {
        int qi = idx >> 8, d = idx & 255;
        Qs[d * 17 + qi] = qkv[(size_t)(q0 + qi) * 3072 + h * 256 + d];
    }
    __syncthreads();

    int qmax = q0 + ATT_BQ - 1;
    int qi   = tid >> 4;

    {
        int kk0 = (tid & 15) * 4;
        for (int s0 = 0; s0 < TLEN; s0 += ATT_KT) {
            if (s0 > qmax) {
                for (int idx = tid; idx < ATT_BQ * ATT_KT; idx += 256) {
                    int rr = idx >> 6, cc = idx & 63;
                    Ss[rr * SPAD + s0 + cc] = -1e30f;
                }
                continue;
            }
            for (int idx = tid; idx < ATT_KT * 256; idx += 256) {
                int kk = idx >> 8, d = idx & 255;
                KV[d * 68 + kk] = qkv[(size_t)(s0 + kk) * 3072 + 1024 + h * 256 + d];
            }
            __syncthreads();
            float a0 = 0.f, a1 = 0.f, a2 = 0.f, a3 = 0.f;
#pragma unroll 4
            for (int d = 0; d < 256; d++) {
                float  qv = Qs[d * 17 + qi];
                float4 kv = *(const float4*)&KV[d * 68 + kk0];
                a0 = fmaf(qv, kv.x, a0);
                a1 = fmaf(qv, kv.y, a1);
                a2 = fmaf(qv, kv.z, a2);
                a3 = fmaf(qv, kv.w, a3);
            }
            int i  = q0 + qi;
            int jb = s0 + kk0;
            float accs[4] = {a0, a1, a2, a3};
#pragma unroll
            for (int c = 0; c < 4; c++) {
                int jj = jb + c;
                float mv = (jj > i) ? -1e30f : (-slope * (float)((i - jj) / 25));
                Ss[qi * SPAD + jj] = accs[c] * 0.0625f + mv;
            }
            __syncthreads();
        }
    }
    __syncthreads();

    {
        int warp = tid >> 5, lane = tid & 31;
        for (int rr = warp; rr < ATT_BQ; rr += 8) {
            float mx = -1e30f;
            for (int jj = lane; jj < TLEN; jj += 32) mx = fmaxf(mx, Ss[rr * SPAD + jj]);
#pragma unroll
            for (int o = 16; o; o >>= 1) mx = fmaxf(mx, __shfl_xor_sync(0xffffffffu, mx, o));
            float sum = 0.0f;
            for (int jj = lane; jj < TLEN; jj += 32) {
                float e = expf(Ss[rr * SPAD + jj] - mx);
                Ss[rr * SPAD + jj] = e;
                sum += e;
            }
#pragma unroll
            for (int o = 16; o; o >>= 1) sum += __shfl_xor_sync(0xffffffffu, sum, o);
            float inv = 1.0f / sum;
            for (int jj = lane; jj < TLEN; jj += 32) Ss[rr * SPAD + jj] *= inv;
        }
    }
    __syncthreads();

    float acc[16];
#pragma unroll
    for (int i = 0; i < 16; i++) acc[i] = 0.0f;
    int d0 = (tid & 15) * 16;

    for (int s0 = 0; s0 <= qmax; s0 += ATT_KT) {
        for (int idx = tid; idx < ATT_KT * 256; idx += 256) {
            int kk = idx >> 8, d = idx & 255;
            KV[kk * 256 + d] = qkv[(size_t)(s0 + kk) * 3072 + 2048 + h * 256 + d];
        }
        __syncthreads();
        for (int kk = 0; kk < ATT_KT; kk++) {
            float a = Ss[qi * SPAD + s0 + kk];
            const float4* vp = (const float4*)&KV[kk * 256 + d0];
            float4 v0 = vp[0], v1 = vp[1], v2 = vp[2], v3 = vp[3];
            acc[0]  = fmaf(a, v0.x, acc[0]);  acc[1]  = fmaf(a, v0.y, acc[1]);
            acc[2]  = fmaf(a, v0.z, acc[2]);  acc[3]  = fmaf(a, v0.w, acc[3]);
            acc[4]  = fmaf(a, v1.x, acc[4]);  acc[5]  = fmaf(a, v1.y, acc[5]);
            acc[6]  = fmaf(a, v1.z, acc[6]);  acc[7]  = fmaf(a, v1.w, acc[7]);
            acc[8]  = fmaf(a, v2.x, acc[8]);  acc[9]  = fmaf(a, v2.y, acc[9]);
            acc[10] = fmaf(a, v2.z, acc[10]); acc[11] = fmaf(a, v2.w, acc[11]);
            acc[12] = fmaf(a, v3.x, acc[12]); acc[13] = fmaf(a, v3.y, acc[13]);
            acc[14] = fmaf(a, v3.z, acc[14]); acc[15] = fmaf(a, v3.w, acc[15]);
        }
        __syncthreads();
    }
#pragma unroll
    for (int c = 0; c < 16; c++)
        split_write(ohi, olo, (size_t)(q0 + qi) * 1024 + h * 256 + d0 + c, acc[c]);
}

// ---------------- launcher ----------------
extern "C" void kernel_launch(void* const* d_in, const int* in_sizes, int n_in,
                              void* d_out, int out_size)
{
    const float* audio   = (const float*)d_in[0];
    const float* vertice = (const float*)d_in[1];
    const float* tmpl    = (const float*)d_in[2];
    const float* one_hot = (const float*)d_in[3];
    const float* W_af    = (const float*)d_in[4];
    const float* b_af    = (const float*)d_in[5];
    const float* W_vm    = (const float*)d_in[6];
    const float* b_vm    = (const float*)d_in[7];
    const float* W_obj   = (const float*)d_in[8];
    const float* Wqkv_sa = (const float*)d_in[9];
    const float* bqkv_sa = (const float*)d_in[10];
    const float* Wo_sa   = (const float*)d_in[11];
    const float* bo_sa   = (const float*)d_in[12];
    const float* Wqkv_ca = (const float*)d_in[13];
    const float* bqkv_ca = (const float*)d_in[14];
    const float* Wo_ca   = (const float*)d_in[15];
    const float* bo_ca   = (const float*)d_in[16];
    const float* W1      = (const float*)d_in[17];
    const float* b1      = (const float*)d_in[18];
    const float* W2      = (const float*)d_in[19];
    const float* b2      = (const float*)d_in[20];
    const float* g1      = (const float*)d_in[21];
    const float* be1     = (const float*)d_in[22];
    const float* g2      = (const float*)d_in[23];
    const float* be2     = (const float*)d_in[24];
    const float* g3      = (const float*)d_in[25];
    const float* be3     = (const float*)d_in[26];
    const float* W_vr    = (const float*)d_in[27];
    const float* b_vr    = (const float*)d_in[28];
    float* out = (float*)d_out;

    float *style, *x, *y, *qkv, *part;
    cudaGetSymbolAddress((void**)&style, g_style);
    cudaGetSymbolAddress((void**)&x,     g_x);
    cudaGetSymbolAddress((void**)&y,     g_y);
    cudaGetSymbolAddress((void**)&qkv,   g_qkv);
    cudaGetSymbolAddress((void**)&part,  g_part);

#define SYM(p, s) bf16* p; cudaGetSymbolAddress((void**)&p, s)
    SYM(Waf_h, g_Waf_h);  SYM(Waf_l, g_Waf_l);
    SYM(Wvm_h, g_Wvm_h);  SYM(Wvm_l, g_Wvm_l);
    SYM(Wqkv_h, g_Wqkv_h); SYM(Wqkv_l, g_Wqkv_l);
    SYM(Wosa_h, g_Wosa_h); SYM(Wosa_l, g_Wosa_l);
    SYM(Wvca_h, g_Wvca_h); SYM(Wvca_l, g_Wvca_l);
    SYM(Woca_h, g_Woca_h); SYM(Woca_l, g_Woca_l);
    SYM(W1_h, g_W1_h);    SYM(W1_l, g_W1_l);
    SYM(W2_h, g_W2_h);    SYM(W2_l, g_W2_l);
    SYM(Wvr_h, g_Wvr_h);  SYM(Wvr_l, g_Wvr_l);
    SYM(aud_h, g_aud_h);  SYM(aud_l, g_aud_l);
    SYM(vin_h, g_vin_h);  SYM(vin_l, g_vin_l);
    SYM(hid_h, g_hid_h);  SYM(hid_l, g_hid_l);
    SYM(xa_h, g_xa_h);    SYM(xa_l, g_xa_l);
    SYM(x2_h, g_x2_h);    SYM(x2_l, g_x2_l);
    SYM(y2_h, g_y2_h);    SYM(y2_l, g_y2_l);
    SYM(attn_h, g_attn_h); SYM(attn_l, g_attn_l);
    SYM(vca_h, g_vca_h);  SYM(vca_l, g_vca_l);
    SYM(ff_h, g_ff_h);    SYM(ff_l, g_ff_l);
#undef SYM

    cudaFuncSetAttribute(attention_sa,
        cudaFuncAttributeMaxDynamicSharedMemorySize, ATT_SMEM_BYTES);
    cudaFuncSetAttribute(mma_gemm2<0>,
        cudaFuncAttributeMaxDynamicSharedMemorySize, GEMM_SMEM_BYTES);
    cudaFuncSetAttribute(mma_gemm2<4>,
        cudaFuncAttributeMaxDynamicSharedMemorySize, GEMM_SMEM_BYTES);

    const int M = TLEN;

    // ---- single merged conversion launch ----
    {
        ConvJobs J;
        J.tmpl = tmpl;
        const float* srcs[NJOBS] = { W_af, audio, W_vm, vertice, Wqkv_sa,
                                     Wo_sa, Wqkv_ca + (size_t)2048*DMODEL, Wo_ca,
                                     W1, W2, W_vr };
        bf16* his[NJOBS] = { Waf_h, aud_h, Wvm_h, vin_h, Wqkv_h, Wosa_h, Wvca_h,
                             Woca_h, W1_h, W2_h, Wvr_h };
        bf16* los[NJOBS] = { Waf_l, aud_l, Wvm_l, vin_l, Wqkv_l, Wosa_l, Wvca_l,
                             Woca_l, W1_l, W2_l, Wvr_l };
        int Ks[NJOBS]    = { AUDDIM, AUDDIM, V3DIM, V3DIM, DMODEL, DMODEL, DMODEL,
                             DMODEL, DMODEL, DFFDIM, DMODEL };
        int Kps[NJOBS]   = { AUDDIM, AUDDIM, KVPAD, KVPAD, DMODEL, DMODEL, DMODEL,
                             DMODEL, DMODEL, DFFDIM, DMODEL };
        int rows[NJOBS]  = { DMODEL, TLEN, DMODEL, TLEN, 3*DMODEL, DMODEL, DMODEL,
                             DMODEL, DFFDIM, DMODEL, V3DIM };
        int modes[NJOBS] = { 0, 0, 0, 1, 0, 0, 0, 0, 0, 0, 0 };
        int nb = 0;
        for (int t = 0; t < NJOBS; t++) {
            J.src[t] = srcs[t]; J.hi[t] = his[t]; J.lo[t] = los[t];
            J.K[t] = Ks[t]; J.Kpad[t] = Kps[t]; J.mode[t] = modes[t];
            J.total[t] = (long)rows[t] * Kps[t];
            nb += (int)((J.total[t] + 4095) / 4096);
            J.blk_end[t] = nb;
        }
        conv_all<<<nb, 256>>>(J);
    }
    style_k<<<4, 256>>>(one_hot, W_obj, style);

    // ---- hidden = audio @ W_af^T + b_af  (24 chunks, split 6 -> 192 CTAs) ----
    mma_gemm2<0><<<dim3(8,4,6), 256, GEMM_SMEM_BYTES>>>(
        aud_h, aud_l, Waf_h, Waf_l, nullptr, nullptr,
        nullptr, part, M, DMODEL, AUDDIM, 24, 6);
    reduce_epi<0><<<(M*DMODEL/4+255)/256, 256>>>(part, b_af, nullptr, nullptr,
        nullptr, hid_h, hid_l, M, DMODEL, 6);

    // ---- x = vin @ W_vm^T + b_vm + style + PE  (472 chunks, split 9 -> 288 CTAs) ----
    mma_gemm2<0><<<dim3(8,4,9), 256, GEMM_SMEM_BYTES>>>(
        vin_h, vin_l, Wvm_h, Wvm_l, nullptr, nullptr,
        nullptr, part, M, DMODEL, KVPAD, 472, 9);
    reduce_epi<3><<<(M*DMODEL/4+255)/256, 256>>>(part, b_vm, nullptr, style,
        x, xa_h, xa_l, M, DMODEL, 9);

    // ---- qkv  (32 chunks, split 3 -> 288 CTAs) ----
    mma_gemm2<0><<<dim3(24,4,3), 256, GEMM_SMEM_BYTES>>>(
        xa_h, xa_l, Wqkv_h, Wqkv_l, nullptr, nullptr,
        nullptr, part, M, 3*DMODEL, DMODEL, 32, 3);
    reduce_epi<0><<<(M*3*DMODEL/4+255)/256, 256>>>(part, bqkv_sa, nullptr, nullptr,
        qkv, nullptr, nullptr, M, 3*DMODEL, 3);

    attention_sa<<<dim3(TLEN/ATT_BQ, NHEAD), 256, ATT_SMEM_BYTES>>>(qkv, attn_h, attn_l);

    // ---- y = LN1(x + attn @ Wo_sa^T + bo_sa)  (32 chunks, split 8 -> 256 CTAs) ----
    mma_gemm2<0><<<dim3(8,4,8), 256, GEMM_SMEM_BYTES>>>(
        attn_h, attn_l, Wosa_h, Wosa_l, nullptr, nullptr,
        nullptr, part, M, DMODEL, DMODEL, 32, 8);
    reduce_ln<<<M, 256>>>(part, bo_sa, x, g1, be1, y, nullptr, nullptr, 8);

    // ---- cross-attn (diagonal)  (split 8) ----
    mma_gemm2<0><<<dim3(8,4,8), 256, GEMM_SMEM_BYTES>>>(
        hid_h, hid_l, Wvca_h, Wvca_l, nullptr, nullptr,
        nullptr, part, M, DMODEL, DMODEL, 32, 8);
    reduce_epi<0><<<(M*DMODEL/4+255)/256, 256>>>(part, bqkv_ca + 2048, nullptr, nullptr,
        nullptr, vca_h, vca_l, M, DMODEL, 8);
    mma_gemm2<0><<<dim3(8,4,8), 256, GEMM_SMEM_BYTES>>>(
        vca_h, vca_l, Woca_h, Woca_l, nullptr, nullptr,
        nullptr, part, M, DMODEL, DMODEL, 32, 8);
    reduce_ln<<<M, 256>>>(part, bo_ca, y, g2, be2, x, x2_h, x2_l, 8);

    // ---- FFN  (ffn1 split 4 -> 256 CTAs, ffn2 split 8 -> 256 CTAs) ----
    mma_gemm2<0><<<dim3(16,4,4), 256, GEMM_SMEM_BYTES>>>(
        x2_h, x2_l, W1_h, W1_l, nullptr, nullptr,
        nullptr, part, M, DFFDIM, DMODEL, 32, 4);
    reduce_epi<1><<<(M*DFFDIM/4+255)/256, 256>>>(part, b1, nullptr, nullptr,
        nullptr, ff_h, ff_l, M, DFFDIM, 4);
    mma_gemm2<0><<<dim3(8,4,8), 256, GEMM_SMEM_BYTES>>>(
        ff_h, ff_l, W2_h, W2_l, nullptr, nullptr,
        nullptr, part, M, DMODEL, DFFDIM, 64, 8);
    reduce_ln<<<M, 256>>>(part, b2, x, g3, be3, nullptr, y2_h, y2_l, 8);

    // ---- out = y2 @ W_vr^T + b_vr + template ----
    mma_gemm2<4><<<dim3((V3DIM+127)/128, 4, 1), 256, GEMM_SMEM_BYTES>>>(
        y2_h, y2_l, Wvr_h, Wvr_l, b_vr, tmpl,
        out, nullptr, M, V3DIM, DMODEL, 32, 1);
}